// round 14
// baseline (speedup 1.0000x reference)
#include <cuda_runtime.h>
#include <cuda_bf16.h>
#include <math.h>
#include <stdint.h>

// ---------------- static config ----------------
#define BATCH  2
#define CDIM   96
#define HEADS  3
#define INNER  96
#define NWIN   1024
#define NTOK   128
#define MROWS  (BATCH*NWIN*NTOK)   // 262144
#define MLPD   384
#define QKVN   288
#define ATT_SCALE 0.17677669529663687f
#define LOG2E     1.4426950408889634f

typedef __nv_bfloat16 bf16;

// ---------------- scratch ----------------
__device__ bf16 g_hw  [(size_t)MROWS * CDIM];
__device__ bf16 g_qkv [(size_t)MROWS * QKVN];
__device__ bf16 g_attn[(size_t)MROWS * INNER];
__device__ uint32_t g_wqkvT[QKVN * 48];
__device__ uint32_t g_w1T  [MLPD * 48];
__device__ uint32_t g_w2T  [96 * 192];
__device__ uint32_t g_woutT[96 * 48];
__device__ bf16 g_biasTiles[24 * 128 * 128];

__device__ __forceinline__ size_t nat_index(int r) {
    int bb  = r >> 17;
    int rem = r & 131071;
    int wdx = rem >> 7, n = rem & 127;
    int wz = wdx >> 8, wy = (wdx >> 4) & 15, wx = wdx & 15;
    int td = n >> 6,  th = (n >> 3) & 7,   tw = n & 7;
    int sd = (wz * 2 + td + 1) & 7;
    int sh = (wy * 8 + th + 4) & 127;
    int sw = (wx * 8 + tw + 4) & 127;
    return ((((size_t)bb * 8 + sd) << 7) | sh) << 7 | sw;
}

__device__ __forceinline__ float gelu_tanh(float v) {
    float c = v + 0.044715f * v * v * v;
    return 0.5f * v * (1.0f + tanhf(0.7978845608028654f * c));
}

__device__ __forceinline__ uint32_t packbf(float a, float b) {
    __nv_bfloat162 h = __floats2bfloat162_rn(a, b);
    return *reinterpret_cast<uint32_t*>(&h);
}

__device__ __forceinline__ float2 unpackbf(uint32_t u) {
    __nv_bfloat162 h = *reinterpret_cast<__nv_bfloat162*>(&u);
    return __bfloat1622float2(h);
}

__device__ __forceinline__ uint32_t sm_addr(const void* p) {
    return (uint32_t)__cvta_generic_to_shared(p);
}

#define MMA_BF16(d, a0, a1, a2, a3, b0, b1)                                   \
    asm volatile(                                                             \
        "mma.sync.aligned.m16n8k16.row.col.f32.bf16.bf16.f32 "                \
        "{%0,%1,%2,%3}, {%4,%5,%6,%7}, {%8,%9}, {%0,%1,%2,%3};\n"             \
        : "+f"(d[0]), "+f"(d[1]), "+f"(d[2]), "+f"(d[3])                      \
        : "r"(a0), "r"(a1), "r"(a2), "r"(a3), "r"(b0), "r"(b1))

#define LDSM_X4(d0, d1, d2, d3, a)                                            \
    asm volatile("ldmatrix.sync.aligned.m8n8.x4.shared.b16 {%0,%1,%2,%3}, [%4];" \
        : "=r"(d0), "=r"(d1), "=r"(d2), "=r"(d3) : "r"(a))

#define LDSM_X2(d0, d1, a)                                                    \
    asm volatile("ldmatrix.sync.aligned.m8n8.x2.shared.b16 {%0,%1}, [%2];"    \
        : "=r"(d0), "=r"(d1) : "r"(a))

#define CP_ASYNC16(dst, src)                                                  \
    asm volatile("cp.async.cg.shared.global [%0], [%1], 16;"                  \
        :: "r"(dst), "l"(src))
#define CP_COMMIT() asm volatile("cp.async.commit_group;")
#define CP_WAIT0()  asm volatile("cp.async.wait_group 0;")
#define CP_WAIT1()  asm volatile("cp.async.wait_group 1;")

__device__ __forceinline__ uint32_t a_frag_addr(const uint32_t* base, int S,
                                                int R, int kk, int lane) {
    return sm_addr(base + (R + (lane & 15)) * S + kk * 8 + ((lane >> 4) << 2));
}
__device__ __forceinline__ uint32_t b_frag_addr(const uint32_t* base, int S,
                                                int n0, int kk, int lane) {
    return sm_addr(base + (n0 + ((lane >> 4) << 3) + (lane & 7)) * S +
                   kk * 8 + (((lane >> 3) & 1) << 2));
}

// ---------------- merged weight convert ----------------
__global__ void convAll(const float* __restrict__ wqkv, const float* __restrict__ w1,
                        const float* __restrict__ w2, const float* __restrict__ wout,
                        uint32_t* __restrict__ oqkv, uint32_t* __restrict__ o1,
                        uint32_t* __restrict__ o2, uint32_t* __restrict__ oo) {
    int idx = blockIdx.x * 256 + threadIdx.x;
    if (idx < 13824) {
        int n = idx / 48, c = idx - n * 48;
        oqkv[idx] = packbf(wqkv[(2 * c) * QKVN + n], wqkv[(2 * c + 1) * QKVN + n]);
    } else if ((idx -= 13824) < 18432) {
        int n = idx / 48, c = idx - n * 48;
        o1[idx] = packbf(w1[(2 * c) * MLPD + n], w1[(2 * c + 1) * MLPD + n]);
    } else if ((idx -= 18432) < 18432) {
        int n = idx / 192, c = idx - n * 192;
        o2[idx] = packbf(w2[(2 * c) * 96 + n], w2[(2 * c + 1) * 96 + n]);
    } else if ((idx -= 18432) < 4608) {
        int n = idx / 48, c = idx - n * 48;
        oo[idx] = packbf(wout[(2 * c) * 96 + n], wout[(2 * c + 1) * 96 + n]);
    }
}

// ---------------- bias+mask tile precompute ----------------
__global__ void bias_tiles_kernel(const float* __restrict__ relb,
                                  bf16* __restrict__ tiles) {
    int idx = blockIdx.x * 256 + threadIdx.x;
    int tile = idx >> 14;
    int rem  = idx & 16383;
    int ii = rem >> 7, jj = rem & 127;
    int head = tile >> 3, cls = tile & 7;
    int di = ii >> 6, hi = (ii >> 3) & 7, wi = ii & 7;
    int dj = jj >> 6, hj = (jj >> 3) & 7, wj = jj & 7;
    int ri = ((cls & 4) ? (1 + di) : 0) * 9 +
             ((cls & 2) ? ((hi < 4) ? 1 : 2) : 0) * 3 +
             ((cls & 1) ? ((wi < 4) ? 1 : 2) : 0);
    int rj = ((cls & 4) ? (1 + dj) : 0) * 9 +
             ((cls & 2) ? ((hj < 4) ? 1 : 2) : 0) * 3 +
             ((cls & 1) ? ((wj < 4) ? 1 : 2) : 0);
    int bidx = (di - dj + 1) * 225 + (hi - hj + 7) * 15 + (wi - wj + 7);
    float v = relb[bidx * 3 + head] * LOG2E + (ri == rj ? 0.f : -1e9f);
    tiles[idx] = __float2bfloat16(v);
}

// ---------------- LayerNorm (warp per token), bf16 output ----------------
template<bool GATHER>
__global__ void ln_kernel(const float* __restrict__ x,
                          const float* __restrict__ gamma,
                          const float* __restrict__ beta,
                          bf16* __restrict__ out) {
    int warp = (blockIdx.x * blockDim.x + threadIdx.x) >> 5;
    int lane = threadIdx.x & 31;
    if (warp >= MROWS) return;
    size_t src = GATHER ? nat_index(warp) : (size_t)warp;
    const float* xp = x + src * CDIM;
    float v0 = xp[lane], v1 = xp[lane + 32], v2 = xp[lane + 64];
    float s = v0 + v1 + v2;
#pragma unroll
    for (int o = 16; o; o >>= 1) s += __shfl_xor_sync(0xffffffffu, s, o);
    float mu = s * (1.0f / 96.0f);
    float d0 = v0 - mu, d1 = v1 - mu, d2 = v2 - mu;
    float q = d0 * d0 + d1 * d1 + d2 * d2;
#pragma unroll
    for (int o = 16; o; o >>= 1) q += __shfl_xor_sync(0xffffffffu, q, o);
    float rs = rsqrtf(q * (1.0f / 96.0f) + 1e-5f);
    bf16* op = out + (size_t)warp * CDIM;
    op[lane]      = __float2bfloat16(d0 * rs * gamma[lane]      + beta[lane]);
    op[lane + 32] = __float2bfloat16(d1 * rs * gamma[lane + 32] + beta[lane + 32]);
    op[lane + 64] = __float2bfloat16(d2 * rs * gamma[lane + 64] + beta[lane + 64]);
}

// ============ qkv GEMM (128 rows, K=96, N=288): cp.async double-buffered B =====
#define QKV_DSM ((128 * 52 + 2 * 96 * 52) * 4)
__global__ void __launch_bounds__(256)
qkv_gemm(const bf16* __restrict__ A, const uint32_t* __restrict__ BT,
         uint32_t* __restrict__ Cv) {
    extern __shared__ uint32_t dsm[];
    uint32_t* As = dsm;
    uint32_t* Bsb[2] = { dsm + 128 * 52, dsm + 128 * 52 + 96 * 52 };
    int tid = threadIdx.x;
    int lane = tid & 31, wid = tid >> 5;
    int wm = wid & 3, wn = wid >> 2;
    int g = lane >> 2, t = lane & 3;
    int row0 = blockIdx.x * 128;

    {
        const float4* src = (const float4*)(A + (size_t)row0 * CDIM);
#pragma unroll
        for (int i = 0; i < 6; i++) {
            int lin = tid + i * 256;
            int r = lin / 12, c = lin % 12;
            CP_ASYNC16(sm_addr(As + r * 52 + c * 4), src + lin);
        }
    }
    {
        const float4* src = (const float4*)BT;
#pragma unroll
        for (int i = 0; i < 5; i++) {
            int lin = tid + i * 256;
            if (lin < 1152) {
                int r = lin / 12, c = lin % 12;
                CP_ASYNC16(sm_addr(Bsb[0] + r * 52 + c * 4), src + lin);
            }
        }
    }
    CP_COMMIT();
    CP_WAIT0();
    __syncthreads();

#pragma unroll 1
    for (int nt = 0; nt < 3; nt++) {
        uint32_t* Bs = Bsb[nt & 1];
        if (nt < 2) {
            const float4* src = (const float4*)(BT + (size_t)(nt + 1) * 96 * 48);
            uint32_t* Bn = Bsb[(nt + 1) & 1];
#pragma unroll
            for (int i = 0; i < 5; i++) {
                int lin = tid + i * 256;
                if (lin < 1152) {
                    int r = lin / 12, c = lin % 12;
                    CP_ASYNC16(sm_addr(Bn + r * 52 + c * 4), src + lin);
                }
            }
            CP_COMMIT();
        }

        float acc[2][6][4];
#pragma unroll
        for (int a = 0; a < 2; a++)
#pragma unroll
            for (int b = 0; b < 6; b++)
#pragma unroll
                for (int c = 0; c < 4; c++) acc[a][b][c] = 0.0f;

#pragma unroll
        for (int kk = 0; kk < 6; kk++) {
            uint32_t af[2][4];
#pragma unroll
            for (int mi = 0; mi < 2; mi++)
                LDSM_X4(af[mi][0], af[mi][1], af[mi][2], af[mi][3],
                        a_frag_addr(As, 52, wm * 32 + mi * 16, kk, lane));
#pragma unroll
            for (int p = 0; p < 3; p++) {
                uint32_t b0, b1, b2, b3;
                LDSM_X4(b0, b1, b2, b3,
                        b_frag_addr(Bs, 52, wn * 48 + p * 16, kk, lane));
#pragma unroll
                for (int mi = 0; mi < 2; mi++) {
                    MMA_BF16(acc[mi][2 * p],     af[mi][0], af[mi][1], af[mi][2], af[mi][3], b0, b1);
                    MMA_BF16(acc[mi][2 * p + 1], af[mi][0], af[mi][1], af[mi][2], af[mi][3], b2, b3);
                }
            }
        }
        int col0 = nt * 96;
#pragma unroll
        for (int mi = 0; mi < 2; mi++) {
            int rA = row0 + wm * 32 + mi * 16 + g;
            int rB = rA + 8;
#pragma unroll
            for (int ni = 0; ni < 6; ni++) {
                int col = col0 + wn * 48 + ni * 8 + 2 * t;
                Cv[(size_t)rA * 144 + (col >> 1)] = packbf(acc[mi][ni][0], acc[mi][ni][1]);
                Cv[(size_t)rB * 144 + (col >> 1)] = packbf(acc[mi][ni][2], acc[mi][ni][3]);
            }
        }
        if (nt < 2) {
            CP_WAIT0();
            __syncthreads();
        }
    }
}

// ============ FUSED: out-proj + residual + LN2 + fc1 + GELU + fc2 + write ======
// smem (u32): As[0..6656) | Bs[6656..11648)   (phase 1)
//             rowbuf fp32 [0..12800)          (phase 2, aliases As/Bs)
//             H2s[12800..19456) | Ms[19456..24064) | W1b[24064..27392) | W2b[27392..30848)
#define BLK2_DSM (30848 * 4)   // 123392 B
__global__ void __launch_bounds__(256)
block2_kernel(const bf16* __restrict__ A, const uint32_t* __restrict__ BT,
              float* __restrict__ out,
              const float* __restrict__ bias, const float* __restrict__ res,
              const float* __restrict__ gamma, const float* __restrict__ beta,
              const uint32_t* __restrict__ W1T, const float* __restrict__ bias1,
              const uint32_t* __restrict__ W2T, const float* __restrict__ bias2) {
    extern __shared__ uint32_t dsm[];
    uint32_t* As  = dsm;
    uint32_t* Bs  = dsm + 6656;
    float*    rowbuf = (float*)dsm;
    uint32_t* H2s = dsm + 12800;
    bf16*     H2b = (bf16*)H2s;          // row stride 104 bf16 (= 52 u32)
    uint32_t* Ms  = dsm + 19456;
    uint32_t* W1b = dsm + 24064;
    uint32_t* W2b = dsm + 27392;

    int tid = threadIdx.x;
    int lane = tid & 31, wid = tid >> 5;
    int wm = wid & 3, wn = wid >> 2;
    int g = lane >> 2, t = lane & 3;
    int row0 = blockIdx.x * 128;

    const float4* w1f4 = (const float4*)W1T;
    const float4* w2f4 = (const float4*)W2T;

    // group A: attn tile + wout tile
    {
        const float4* src = (const float4*)(A + (size_t)row0 * CDIM);
#pragma unroll
        for (int i = 0; i < 6; i++) {
            int lin = tid + i * 256;
            int r = lin / 12, c = lin % 12;
            CP_ASYNC16(sm_addr(As + r * 52 + c * 4), src + lin);
        }
        const float4* bsrc = (const float4*)BT;
#pragma unroll
        for (int i = 0; i < 5; i++) {
            int lin = tid + i * 256;
            if (lin < 1152) {
                int r = lin / 12, c = lin % 12;
                CP_ASYNC16(sm_addr(Bs + r * 52 + c * 4), bsrc + lin);
            }
        }
    }
    CP_COMMIT();
    // group B: W1 chunk 0 (lands during outproj MMAs)
#pragma unroll
    for (int i = 0; i < 3; i++) {
        int lin = tid + i * 256;
        int n = lin / 12, c = lin % 12;
        CP_ASYNC16(sm_addr(W1b + n * 52 + c * 4), w1f4 + (size_t)n * 12 + c);
    }
    CP_COMMIT();
    CP_WAIT1();           // group A done
    __syncthreads();

    // ---- out-proj MMA ----
    float acc[2][6][4];
#pragma unroll
    for (int a = 0; a < 2; a++)
#pragma unroll
        for (int b = 0; b < 6; b++)
#pragma unroll
            for (int c = 0; c < 4; c++) acc[a][b][c] = 0.0f;

#pragma unroll
    for (int kk = 0; kk < 6; kk++) {
        uint32_t af[2][4];
#pragma unroll
        for (int mi = 0; mi < 2; mi++)
            LDSM_X4(af[mi][0], af[mi][1], af[mi][2], af[mi][3],
                    a_frag_addr(As, 52, wm * 32 + mi * 16, kk, lane));
#pragma unroll
        for (int p = 0; p < 3; p++) {
            uint32_t b0, b1, b2, b3;
            LDSM_X4(b0, b1, b2, b3, b_frag_addr(Bs, 52, wn * 48 + p * 16, kk, lane));
#pragma unroll
            for (int mi = 0; mi < 2; mi++) {
                MMA_BF16(acc[mi][2 * p],     af[mi][0], af[mi][1], af[mi][2], af[mi][3], b0, b1);
                MMA_BF16(acc[mi][2 * p + 1], af[mi][0], af[mi][1], af[mi][2], af[mi][3], b2, b3);
            }
        }
    }
    __syncthreads();   // As/Bs reads done -> rowbuf may overwrite

    // ---- rowbuf = res[nat] + v + bias (fp32 x_new rows) ----
#pragma unroll
    for (int mi = 0; mi < 2; mi++) {
        int lrA = wm * 32 + mi * 16 + g;
        int lrB = lrA + 8;
        size_t natA = nat_index(row0 + lrA) * (size_t)CDIM;
        size_t natB = nat_index(row0 + lrB) * (size_t)CDIM;
#pragma unroll
        for (int ni = 0; ni < 6; ni++) {
            int col = wn * 48 + ni * 8 + 2 * t;
            float b0 = bias[col], b1 = bias[col + 1];
            float2 rx = *(const float2*)(res + natA + col);
            float2 ry = *(const float2*)(res + natB + col);
            *(float2*)(rowbuf + lrA * 100 + col) =
                make_float2(rx.x + acc[mi][ni][0] + b0, rx.y + acc[mi][ni][1] + b1);
            *(float2*)(rowbuf + lrB * 100 + col) =
                make_float2(ry.x + acc[mi][ni][2] + b0, ry.y + acc[mi][ni][3] + b1);
        }
    }
    __syncthreads();

    // ---- LN2: rowbuf -> H2b (smem bf16, stride 104) ----
    {
        float ga0 = gamma[lane], ga1 = gamma[lane + 32], ga2 = gamma[lane + 64];
        float be0 = beta[lane],  be1 = beta[lane + 32],  be2 = beta[lane + 64];
#pragma unroll 1
        for (int it = 0; it < 16; it++) {
            int lr = wid * 16 + it;
            const float* rb = rowbuf + lr * 100;
            float v0 = rb[lane], v1 = rb[lane + 32], v2 = rb[lane + 64];
            float s = v0 + v1 + v2;
#pragma unroll
            for (int o = 16; o; o >>= 1) s += __shfl_xor_sync(0xffffffffu, s, o);
            float mu = s * (1.0f / 96.0f);
            float d0 = v0 - mu, d1 = v1 - mu, d2 = v2 - mu;
            float q = d0 * d0 + d1 * d1 + d2 * d2;
#pragma unroll
            for (int o = 16; o; o >>= 1) q += __shfl_xor_sync(0xffffffffu, q, o);
            float rs = rsqrtf(q * (1.0f / 96.0f) + 1e-5f);
            H2b[lr * 104 + lane]      = __float2bfloat16(d0 * rs * ga0 + be0);
            H2b[lr * 104 + lane + 32] = __float2bfloat16(d1 * rs * ga1 + be1);
            H2b[lr * 104 + lane + 64] = __float2bfloat16(d2 * rs * ga2 + be2);
        }
    }
    CP_WAIT0();           // W1[0] landed (long ago)
    __syncthreads();      // H2s visible

    // ---- MLP chunk pipeline ----
    float acc2[2][6][4];
#pragma unroll
    for (int a = 0; a < 2; a++)
#pragma unroll
        for (int b = 0; b < 6; b++)
#pragma unroll
            for (int c = 0; c < 4; c++) acc2[a][b][c] = 0.0f;

#pragma unroll 1
    for (int nt = 0; nt < 6; nt++) {
        // issue W2[nt] (overlaps fc1)
#pragma unroll
        for (int i = 0; i < 3; i++) {
            int lin = tid + i * 256;
            int n = lin >> 3, c = lin & 7;
            CP_ASYNC16(sm_addr(W2b + n * 36 + c * 4),
                       w2f4 + (size_t)n * 48 + nt * 8 + c);
        }
        CP_COMMIT();

        float acc1[2][4][4];
#pragma unroll
        for (int a = 0; a < 2; a++)
#pragma unroll
            for (int b = 0; b < 4; b++)
#pragma unroll
                for (int c = 0; c < 4; c++) acc1[a][b][c] = 0.0f;

#pragma unroll
        for (int kk = 0; kk < 6; kk++) {
            uint32_t af[2][4];
#pragma unroll
            for (int mi = 0; mi < 2; mi++)
                LDSM_X4(af[mi][0], af[mi][1], af[mi][2], af[mi][3],
                        a_frag_addr(H2s, 52, wm * 32 + mi * 16, kk, lane));
#pragma unroll
            for (int p = 0; p < 2; p++) {
                uint32_t b0, b1, b2, b3;
                LDSM_X4(b0, b1, b2, b3, b_frag_addr(W1b, 52, wn * 32 + p * 16, kk, lane));
#pragma unroll
                for (int mi = 0; mi < 2; mi++) {
                    MMA_BF16(acc1[mi][2 * p],     af[mi][0], af[mi][1], af[mi][2], af[mi][3], b0, b1);
                    MMA_BF16(acc1[mi][2 * p + 1], af[mi][0], af[mi][1], af[mi][2], af[mi][3], b2, b3);
                }
            }
        }
        // GELU -> Ms
#pragma unroll
        for (int mi = 0; mi < 2; mi++) {
            int rA = wm * 32 + mi * 16 + g;
#pragma unroll
            for (int ni = 0; ni < 4; ni++) {
                int lc = wn * 32 + ni * 8 + 2 * t;
                float b0 = bias1[nt * 64 + lc], b1 = bias1[nt * 64 + lc + 1];
                int c2 = lc >> 1;
                Ms[rA * 36 + c2] = packbf(gelu_tanh(acc1[mi][ni][0] + b0),
                                          gelu_tanh(acc1[mi][ni][1] + b1));
                Ms[(rA + 8) * 36 + c2] = packbf(gelu_tanh(acc1[mi][ni][2] + b0),
                                                gelu_tanh(acc1[mi][ni][3] + b1));
            }
        }
        CP_WAIT0();
        __syncthreads();

        if (nt < 5) {
#pragma unroll
            for (int i = 0; i < 3; i++) {
                int lin = tid + i * 256;
                int n = lin / 12, c = lin % 12;
                CP_ASYNC16(sm_addr(W1b + n * 52 + c * 4),
                           w1f4 + (size_t)((nt + 1) * 64 + n) * 12 + c);
            }
            CP_COMMIT();
        }

#pragma unroll
        for (int kk = 0; kk < 4; kk++) {
            uint32_t af[2][4];
#pragma unroll
            for (int mi = 0; mi < 2; mi++)
                LDSM_X4(af[mi][0], af[mi][1], af[mi][2], af[mi][3],
                        a_frag_addr(Ms, 36, wm * 32 + mi * 16, kk, lane));
#pragma unroll
            for (int p = 0; p < 3; p++) {
                uint32_t b0, b1, b2, b3;
                LDSM_X4(b0, b1, b2, b3, b_frag_addr(W2b, 36, wn * 48 + p * 16, kk, lane));
#pragma unroll
                for (int mi = 0; mi < 2; mi++) {
                    MMA_BF16(acc2[mi][2 * p],     af[mi][0], af[mi][1], af[mi][2], af[mi][3], b0, b1);
                    MMA_BF16(acc2[mi][2 * p + 1], af[mi][0], af[mi][1], af[mi][2], af[mi][3], b2, b3);
                }
            }
        }
        if (nt < 5) {
            CP_WAIT0();
            __syncthreads();
        }
    }

    // ---- final: out[nat] = rowbuf + fc2 + bias2 (pure writes) ----
#pragma unroll
    for (int mi = 0; mi < 2; mi++) {
        int lrA = wm * 32 + mi * 16 + g;
        int lrB = lrA + 8;
        size_t natA = nat_index(row0 + lrA) * (size_t)CDIM;
        size_t natB = nat_index(row0 + lrB) * (size_t)CDIM;
#pragma unroll
        for (int ni = 0; ni < 6; ni++) {
            int cc = wn * 48 + ni * 8 + 2 * t;
            float b0 = bias2[cc], b1 = bias2[cc + 1];
            float2 xa = *(const float2*)(rowbuf + lrA * 100 + cc);
            float2 xb = *(const float2*)(rowbuf + lrB * 100 + cc);
            *(float2*)(out + natA + cc) = make_float2(xa.x + acc2[mi][ni][0] + b0,
                                                      xa.y + acc2[mi][ni][1] + b1);
            *(float2*)(out + natB + cc) = make_float2(xb.x + acc2[mi][ni][2] + b0,
                                                      xb.y + acc2[mi][ni][3] + b1);
        }
    }
}

// ---------------- attention (unchanged from R13) ----------------
__global__ void __launch_bounds__(256, 2)
attn_kernel(const bf16* __restrict__ qkv,
            const bf16* __restrict__ biasTiles,
            bf16* __restrict__ attn_out) {
    extern __shared__ uint32_t dsm[];
    uint32_t* Qs   = dsm;
    uint32_t* Ks   = Qs + 128 * 20;
    uint32_t* Vs32 = Ks + 128 * 20;
    uint32_t* Bt   = Vs32 + 2176;
    bf16* VsT = (bf16*)Vs32;

    int blk  = blockIdx.x;
    int head = blk % HEADS;
    int bw   = blk / HEADS;
    int w    = bw & (NWIN - 1);
    int i    = threadIdx.x;
    int lane = i & 31, wm = i >> 5;
    int g = lane >> 2, t = lane & 3;

    const uint32_t* q32 = (const uint32_t*)(qkv + (size_t)bw * NTOK * QKVN);
    const float qscale = ATT_SCALE * LOG2E;

    {
        int cls = (((w >> 8) == 3) ? 4 : 0) | ((((w >> 4) & 15) == 15) ? 2 : 0) |
                  (((w & 15) == 15) ? 1 : 0);
        const float4* tp = (const float4*)(biasTiles + (size_t)(head * 8 + cls) * 16384);
#pragma unroll
        for (int it = 0; it < 8; it++) {
            int lin = i + it * 256;
            int r = lin >> 4, c = lin & 15;
            CP_ASYNC16(sm_addr(Bt + r * 68 + c * 4), tp + lin);
        }
        CP_COMMIT();
    }

#pragma unroll
    for (int it = 0; it < 8; it++) {
        int idx = i + it * 256;
        int r = idx >> 4, c = idx & 15;
        uint32_t qv = q32[(size_t)r * 144 + head * 16 + c];
        float2 qf = unpackbf(qv);
        Qs[r * 20 + c] = packbf(qf.x * qscale, qf.y * qscale);
        Ks[r * 20 + c] = q32[(size_t)r * 144 + 48 + head * 16 + c];
        uint32_t v = q32[(size_t)r * 144 + 96 + head * 16 + c];
        __nv_bfloat162 h = *reinterpret_cast<__nv_bfloat162*>(&v);
        VsT[(2 * c) * 136 + r]     = h.x;
        VsT[(2 * c + 1) * 136 + r] = h.y;
    }
    CP_WAIT0();
    __syncthreads();

    int R0 = wm * 16;
    float accS[16][4];
#pragma unroll
    for (int b = 0; b < 16; b++)
#pragma unroll
        for (int c = 0; c < 4; c++) accS[b][c] = 0.0f;

#pragma unroll
    for (int kk = 0; kk < 2; kk++) {
        uint32_t a0, a1, a2, a3;
        LDSM_X4(a0, a1, a2, a3, a_frag_addr(Qs, 20, R0, kk, lane));
#pragma unroll
        for (int p = 0; p < 8; p++) {
            uint32_t b0, b1, b2, b3;
            LDSM_X4(b0, b1, b2, b3, b_frag_addr(Ks, 20, p * 16, kk, lane));
            MMA_BF16(accS[2 * p],     a0, a1, a2, a3, b0, b1);
            MMA_BF16(accS[2 * p + 1], a0, a1, a2, a3, b2, b3);
        }
    }

    float invA, invB;
    {
        uint32_t baddr = sm_addr(Bt + (R0 + (lane & 15)) * 68);
        float mA = -1e30f, mB = -1e30f;
#pragma unroll
        for (int nj = 0; nj < 16; nj++) {
            uint32_t br0, br1;
            LDSM_X2(br0, br1, baddr + nj * 16);
            float2 fA = unpackbf(br0), fB = unpackbf(br1);
            float v0 = accS[nj][0] + fA.x;
            float v1 = accS[nj][1] + fA.y;
            float v2 = accS[nj][2] + fB.x;
            float v3 = accS[nj][3] + fB.y;
            accS[nj][0] = v0; accS[nj][1] = v1;
            accS[nj][2] = v2; accS[nj][3] = v3;
            mA = fmaxf(mA, fmaxf(v0, v1));
            mB = fmaxf(mB, fmaxf(v2, v3));
        }
        mA = fmaxf(mA, __shfl_xor_sync(0xffffffffu, mA, 1));
        mA = fmaxf(mA, __shfl_xor_sync(0xffffffffu, mA, 2));
        mB = fmaxf(mB, __shfl_xor_sync(0xffffffffu, mB, 1));
        mB = fmaxf(mB, __shfl_xor_sync(0xffffffffu, mB, 2));
        float dA = 0.f, dB = 0.f;
#pragma unroll
        for (int nj = 0; nj < 16; nj++) {
            float p0 = exp2f(accS[nj][0] - mA);
            float p1 = exp2f(accS[nj][1] - mA);
            float p2 = exp2f(accS[nj][2] - mB);
            float p3 = exp2f(accS[nj][3] - mB);
            accS[nj][0] = p0; accS[nj][1] = p1;
            accS[nj][2] = p2; accS[nj][3] = p3;
            dA += p0 + p1; dB += p2 + p3;
        }
        dA += __shfl_xor_sync(0xffffffffu, dA, 1);
        dA += __shfl_xor_sync(0xffffffffu, dA, 2);
        dB += __shfl_xor_sync(0xffffffffu, dB, 1);
        dB += __shfl_xor_sync(0xffffffffu, dB, 2);
        invA = 1.0f / dA;
        invB = 1.0f / dB;
    }

    float accO[4][4];
#pragma unroll
    for (int b = 0; b < 4; b++)
#pragma unroll
        for (int c = 0; c < 4; c++) accO[b][c] = 0.0f;

#pragma unroll
    for (int kkp = 0; kkp < 8; kkp++) {
        uint32_t a0 = packbf(accS[2 * kkp][0],     accS[2 * kkp][1]);
        uint32_t a1 = packbf(accS[2 * kkp][2],     accS[2 * kkp][3]);
        uint32_t a2 = packbf(accS[2 * kkp + 1][0], accS[2 * kkp + 1][1]);
        uint32_t a3 = packbf(accS[2 * kkp + 1][2], accS[2 * kkp + 1][3]);
#pragma unroll
        for (int ni = 0; ni < 4; ni++) {
            int vb = (ni * 8 + g) * 68 + kkp * 8 + t;
            uint32_t b0 = Vs32[vb], b1 = Vs32[vb + 4];
            MMA_BF16(accO[ni], a0, a1, a2, a3, b0, b1);
        }
    }

    uint32_t* o32 = (uint32_t*)attn_out;
    size_t baseA = ((size_t)bw * 128 + R0 + g) * 48 + head * 16;
    size_t baseB = baseA + 8 * 48;
#pragma unroll
    for (int ni = 0; ni < 4; ni++) {
        int c2 = ni * 4 + t;
        o32[baseA + c2] = packbf(accO[ni][0] * invA, accO[ni][1] * invA);
        o32[baseB + c2] = packbf(accO[ni][2] * invB, accO[ni][3] * invB);
    }
}

#define ATTN_DSM ((128*20 + 128*20 + 2176 + 128*68) * 4)

// ---------------- launch ----------------
extern "C" void kernel_launch(void* const* d_in, const int* in_sizes, int n_in,
                              void* d_out, int out_size) {
    const float* x      = (const float*)d_in[0];
    const float* gamma1 = (const float*)d_in[1];
    const float* beta1  = (const float*)d_in[2];
    const float* w_qkv  = (const float*)d_in[3];
    const float* w_out  = (const float*)d_in[4];
    const float* b_out  = (const float*)d_in[5];
    const float* relb   = (const float*)d_in[6];
    const float* gamma2 = (const float*)d_in[7];
    const float* beta2  = (const float*)d_in[8];
    const float* w1     = (const float*)d_in[9];
    const float* b1     = (const float*)d_in[10];
    const float* w2     = (const float*)d_in[11];
    const float* b2     = (const float*)d_in[12];
    float* out = (float*)d_out;

    bf16 *hw, *qkv, *attn, *btiles;
    uint32_t *wqkvT, *w1T, *w2T, *woutT;
    cudaGetSymbolAddress((void**)&hw,     g_hw);
    cudaGetSymbolAddress((void**)&qkv,    g_qkv);
    cudaGetSymbolAddress((void**)&attn,   g_attn);
    cudaGetSymbolAddress((void**)&btiles, g_biasTiles);
    cudaGetSymbolAddress((void**)&wqkvT,  g_wqkvT);
    cudaGetSymbolAddress((void**)&w1T,    g_w1T);
    cudaGetSymbolAddress((void**)&w2T,    g_w2T);
    cudaGetSymbolAddress((void**)&woutT,  g_woutT);

    cudaFuncSetAttribute(attn_kernel,
                         cudaFuncAttributeMaxDynamicSharedMemorySize, ATTN_DSM);
    cudaFuncSetAttribute(qkv_gemm,
                         cudaFuncAttributeMaxDynamicSharedMemorySize, QKV_DSM);
    cudaFuncSetAttribute(block2_kernel,
                         cudaFuncAttributeMaxDynamicSharedMemorySize, BLK2_DSM);

    convAll<<<(55296 + 255) / 256, 256>>>(w_qkv, w1, w2, w_out,
                                          wqkvT, w1T, w2T, woutT);
    bias_tiles_kernel<<<(24 * 16384) / 256, 256>>>(relb, btiles);

    ln_kernel<true><<<MROWS / 8, 256>>>(x, gamma1, beta1, hw);
    qkv_gemm<<<MROWS / 128, 256, QKV_DSM>>>(hw, wqkvT, (uint32_t*)qkv);
    attn_kernel<<<BATCH * NWIN * HEADS, 256, ATTN_DSM>>>(qkv, btiles, attn);
    block2_kernel<<<MROWS / 128, 256, BLK2_DSM>>>(attn, woutT, out,
                                                  b_out, x, gamma2, beta2,
                                                  w1T, b1, w2T, b2);
}

// round 15
// speedup vs baseline: 1.1998x; 1.1998x over previous
#include <cuda_runtime.h>
#include <cuda_bf16.h>
#include <math.h>
#include <stdint.h>

// ---------------- static config ----------------
#define BATCH  2
#define CDIM   96
#define HEADS  3
#define INNER  96
#define NWIN   1024
#define NTOK   128
#define MROWS  (BATCH*NWIN*NTOK)   // 262144
#define MLPD   384
#define QKVN   288
#define ATT_SCALE 0.17677669529663687f
#define LOG2E     1.4426950408889634f

typedef __nv_bfloat16 bf16;

// ---------------- scratch ----------------
__device__ bf16 g_hw  [(size_t)MROWS * CDIM];
__device__ bf16 g_attn[(size_t)MROWS * INNER];
__device__ bf16 g_h2  [(size_t)MROWS * CDIM];
__device__ uint32_t g_wqkvT[QKVN * 48];
__device__ uint32_t g_w1T  [MLPD * 48];
__device__ uint32_t g_w2T  [96 * 192];
__device__ uint32_t g_woutT[96 * 48];
__device__ bf16 g_biasTiles[24 * 128 * 128];

__device__ __forceinline__ size_t nat_index(int r) {
    int bb  = r >> 17;
    int rem = r & 131071;
    int wdx = rem >> 7, n = rem & 127;
    int wz = wdx >> 8, wy = (wdx >> 4) & 15, wx = wdx & 15;
    int td = n >> 6,  th = (n >> 3) & 7,   tw = n & 7;
    int sd = (wz * 2 + td + 1) & 7;
    int sh = (wy * 8 + th + 4) & 127;
    int sw = (wx * 8 + tw + 4) & 127;
    return ((((size_t)bb * 8 + sd) << 7) | sh) << 7 | sw;
}

__device__ __forceinline__ float gelu_tanh(float v) {
    float c = v + 0.044715f * v * v * v;
    return 0.5f * v * (1.0f + tanhf(0.7978845608028654f * c));
}

__device__ __forceinline__ uint32_t packbf(float a, float b) {
    __nv_bfloat162 h = __floats2bfloat162_rn(a, b);
    return *reinterpret_cast<uint32_t*>(&h);
}

__device__ __forceinline__ float2 unpackbf(uint32_t u) {
    __nv_bfloat162 h = *reinterpret_cast<__nv_bfloat162*>(&u);
    return __bfloat1622float2(h);
}

__device__ __forceinline__ uint32_t sm_addr(const void* p) {
    return (uint32_t)__cvta_generic_to_shared(p);
}

#define MMA_BF16(d, a0, a1, a2, a3, b0, b1)                                   \
    asm volatile(                                                             \
        "mma.sync.aligned.m16n8k16.row.col.f32.bf16.bf16.f32 "                \
        "{%0,%1,%2,%3}, {%4,%5,%6,%7}, {%8,%9}, {%0,%1,%2,%3};\n"             \
        : "+f"(d[0]), "+f"(d[1]), "+f"(d[2]), "+f"(d[3])                      \
        : "r"(a0), "r"(a1), "r"(a2), "r"(a3), "r"(b0), "r"(b1))

#define LDSM_X4(d0, d1, d2, d3, a)                                            \
    asm volatile("ldmatrix.sync.aligned.m8n8.x4.shared.b16 {%0,%1,%2,%3}, [%4];" \
        : "=r"(d0), "=r"(d1), "=r"(d2), "=r"(d3) : "r"(a))

#define LDSM_X2(d0, d1, a)                                                    \
    asm volatile("ldmatrix.sync.aligned.m8n8.x2.shared.b16 {%0,%1}, [%2];"    \
        : "=r"(d0), "=r"(d1) : "r"(a))

#define CP_ASYNC16(dst, src)                                                  \
    asm volatile("cp.async.cg.shared.global [%0], [%1], 16;"                  \
        :: "r"(dst), "l"(src))
#define CP_COMMIT() asm volatile("cp.async.commit_group;")
#define CP_WAIT0()  asm volatile("cp.async.wait_group 0;")
#define CP_WAIT2()  asm volatile("cp.async.wait_group 2;")

__device__ __forceinline__ uint32_t a_frag_addr(const uint32_t* base, int S,
                                                int R, int kk, int lane) {
    return sm_addr(base + (R + (lane & 15)) * S + kk * 8 + ((lane >> 4) << 2));
}
__device__ __forceinline__ uint32_t b_frag_addr(const uint32_t* base, int S,
                                                int n0, int kk, int lane) {
    return sm_addr(base + (n0 + ((lane >> 4) << 3) + (lane & 7)) * S +
                   kk * 8 + (((lane >> 3) & 1) << 2));
}

// ---------------- merged weight convert ----------------
__global__ void convAll(const float* __restrict__ wqkv, const float* __restrict__ w1,
                        const float* __restrict__ w2, const float* __restrict__ wout,
                        uint32_t* __restrict__ oqkv, uint32_t* __restrict__ o1,
                        uint32_t* __restrict__ o2, uint32_t* __restrict__ oo) {
    int idx = blockIdx.x * 256 + threadIdx.x;
    if (idx < 13824) {
        int n = idx / 48, c = idx - n * 48;
        oqkv[idx] = packbf(wqkv[(2 * c) * QKVN + n], wqkv[(2 * c + 1) * QKVN + n]);
    } else if ((idx -= 13824) < 18432) {
        int n = idx / 48, c = idx - n * 48;
        o1[idx] = packbf(w1[(2 * c) * MLPD + n], w1[(2 * c + 1) * MLPD + n]);
    } else if ((idx -= 18432) < 18432) {
        int n = idx / 192, c = idx - n * 192;
        o2[idx] = packbf(w2[(2 * c) * 96 + n], w2[(2 * c + 1) * 96 + n]);
    } else if ((idx -= 18432) < 4608) {
        int n = idx / 48, c = idx - n * 48;
        oo[idx] = packbf(wout[(2 * c) * 96 + n], wout[(2 * c + 1) * 96 + n]);
    }
}

// ---------------- bias+mask tile precompute ----------------
__global__ void bias_tiles_kernel(const float* __restrict__ relb,
                                  bf16* __restrict__ tiles) {
    int idx = blockIdx.x * 256 + threadIdx.x;
    int tile = idx >> 14;
    int rem  = idx & 16383;
    int ii = rem >> 7, jj = rem & 127;
    int head = tile >> 3, cls = tile & 7;
    int di = ii >> 6, hi = (ii >> 3) & 7, wi = ii & 7;
    int dj = jj >> 6, hj = (jj >> 3) & 7, wj = jj & 7;
    int ri = ((cls & 4) ? (1 + di) : 0) * 9 +
             ((cls & 2) ? ((hi < 4) ? 1 : 2) : 0) * 3 +
             ((cls & 1) ? ((wi < 4) ? 1 : 2) : 0);
    int rj = ((cls & 4) ? (1 + dj) : 0) * 9 +
             ((cls & 2) ? ((hj < 4) ? 1 : 2) : 0) * 3 +
             ((cls & 1) ? ((wj < 4) ? 1 : 2) : 0);
    int bidx = (di - dj + 1) * 225 + (hi - hj + 7) * 15 + (wi - wj + 7);
    float v = relb[bidx * 3 + head] * LOG2E + (ri == rj ? 0.f : -1e9f);
    tiles[idx] = __float2bfloat16(v);
}

// ---------------- LayerNorm (warp per token), bf16 output ----------------
template<bool GATHER>
__global__ void ln_kernel(const float* __restrict__ x,
                          const float* __restrict__ gamma,
                          const float* __restrict__ beta,
                          bf16* __restrict__ out) {
    int warp = (blockIdx.x * blockDim.x + threadIdx.x) >> 5;
    int lane = threadIdx.x & 31;
    if (warp >= MROWS) return;
    size_t src = GATHER ? nat_index(warp) : (size_t)warp;
    const float* xp = x + src * CDIM;
    float v0 = xp[lane], v1 = xp[lane + 32], v2 = xp[lane + 64];
    float s = v0 + v1 + v2;
#pragma unroll
    for (int o = 16; o; o >>= 1) s += __shfl_xor_sync(0xffffffffu, s, o);
    float mu = s * (1.0f / 96.0f);
    float d0 = v0 - mu, d1 = v1 - mu, d2 = v2 - mu;
    float q = d0 * d0 + d1 * d1 + d2 * d2;
#pragma unroll
    for (int o = 16; o; o >>= 1) q += __shfl_xor_sync(0xffffffffu, q, o);
    float rs = rsqrtf(q * (1.0f / 96.0f) + 1e-5f);
    bf16* op = out + (size_t)warp * CDIM;
    op[lane]      = __float2bfloat16(d0 * rs * gamma[lane]      + beta[lane]);
    op[lane + 32] = __float2bfloat16(d1 * rs * gamma[lane + 32] + beta[lane + 32]);
    op[lane + 64] = __float2bfloat16(d2 * rs * gamma[lane + 64] + beta[lane + 64]);
}

// ============ FUSED qkv GEMM + 3-head windowed attention (one CTA = window) ====
// smem u32 offsets:
#define QA_QK   0        // 3 heads x (Qs 128x20 | Ks 128x20) = 15360
#define QA_VST  15360    // 3 heads x VsT 32x136 bf16 (2176 u32) = 6528
#define QA_AS   21888    // A tile 128x52 = 6656
#define QA_BS0  28544    // B tile buf0 96x52 = 4992
#define QA_BS1  33536    // B tile buf1
#define QA_BT0  38528    // bias tile buf0 128x68 = 8704
#define QA_BT1  47232    // bias tile buf1
#define QA_DSM  (55936 * 4)   // 223744 B

__global__ void __launch_bounds__(256)
qkv_attn_kernel(const bf16* __restrict__ A, const uint32_t* __restrict__ BT,
                const bf16* __restrict__ biasTiles,
                bf16* __restrict__ attn_out) {
    extern __shared__ uint32_t dsm[];
    int bw  = blockIdx.x;
    int w   = bw & (NWIN - 1);
    int tid = threadIdx.x;
    int lane = tid & 31, wid = tid >> 5;
    int wm = wid & 3, wn = wid >> 2;
    int g = lane >> 2, t = lane & 3;
    int row0 = bw * 128;

    int cls = (((w >> 8) == 3) ? 4 : 0) | ((((w >> 4) & 15) == 15) ? 2 : 0) |
              (((w & 15) == 15) ? 1 : 0);

    uint32_t* As = dsm + QA_AS;
    uint32_t* Bsb[2] = { dsm + QA_BS0, dsm + QA_BS1 };

    // G1: A tile (this window's 128 hw rows) + B tile 0 (Q weights)
    {
        const float4* src = (const float4*)(A + (size_t)row0 * CDIM);
#pragma unroll
        for (int i = 0; i < 6; i++) {
            int lin = tid + i * 256;
            int r = lin / 12, c = lin % 12;
            CP_ASYNC16(sm_addr(As + r * 52 + c * 4), src + lin);
        }
        const float4* bsrc = (const float4*)BT;
#pragma unroll
        for (int i = 0; i < 5; i++) {
            int lin = tid + i * 256;
            if (lin < 1152) {
                int r = lin / 12, c = lin % 12;
                CP_ASYNC16(sm_addr(Bsb[0] + r * 52 + c * 4), bsrc + lin);
            }
        }
    }
    CP_COMMIT();
    // G2, G3: bias tiles for heads 0 and 1 (land during the GEMM phase)
#pragma unroll
    for (int h = 0; h < 2; h++) {
        const float4* tp = (const float4*)(biasTiles + (size_t)(h * 8 + cls) * 16384);
        uint32_t* Bt = dsm + (h ? QA_BT1 : QA_BT0);
#pragma unroll
        for (int it = 0; it < 8; it++) {
            int lin = tid + it * 256;
            int r = lin >> 4, c = lin & 15;
            CP_ASYNC16(sm_addr(Bt + r * 68 + c * 4), tp + lin);
        }
        CP_COMMIT();
    }
    CP_WAIT2();            // G1 done (biases may still fly)
    __syncthreads();

    const float qs = ATT_SCALE * LOG2E;

    // ---- qkv GEMM: 3 column tiles (Q | K | V), epilogue into smem ----
#pragma unroll 1
    for (int nt = 0; nt < 3; nt++) {
        uint32_t* Bs = Bsb[nt & 1];
        if (nt < 2) {
            const float4* src = (const float4*)(BT + (size_t)(nt + 1) * 96 * 48);
            uint32_t* Bn = Bsb[(nt + 1) & 1];
#pragma unroll
            for (int i = 0; i < 5; i++) {
                int lin = tid + i * 256;
                if (lin < 1152) {
                    int r = lin / 12, c = lin % 12;
                    CP_ASYNC16(sm_addr(Bn + r * 52 + c * 4), src + lin);
                }
            }
            CP_COMMIT();
        }

        float acc[2][6][4];
#pragma unroll
        for (int a = 0; a < 2; a++)
#pragma unroll
            for (int b = 0; b < 6; b++)
#pragma unroll
                for (int c = 0; c < 4; c++) acc[a][b][c] = 0.0f;

#pragma unroll
        for (int kk = 0; kk < 6; kk++) {
            uint32_t af[2][4];
#pragma unroll
            for (int mi = 0; mi < 2; mi++)
                LDSM_X4(af[mi][0], af[mi][1], af[mi][2], af[mi][3],
                        a_frag_addr(As, 52, wm * 32 + mi * 16, kk, lane));
#pragma unroll
            for (int p = 0; p < 3; p++) {
                uint32_t b0, b1, b2, b3;
                LDSM_X4(b0, b1, b2, b3,
                        b_frag_addr(Bs, 52, wn * 48 + p * 16, kk, lane));
#pragma unroll
                for (int mi = 0; mi < 2; mi++) {
                    MMA_BF16(acc[mi][2 * p],     af[mi][0], af[mi][1], af[mi][2], af[mi][3], b0, b1);
                    MMA_BF16(acc[mi][2 * p + 1], af[mi][0], af[mi][1], af[mi][2], af[mi][3], b2, b3);
                }
            }
        }

        // epilogue -> smem (Q scaled, K plain, V transposed)
        if (nt < 2) {
#pragma unroll
            for (int mi = 0; mi < 2; mi++) {
                int rAl = wm * 32 + mi * 16 + g;
#pragma unroll
                for (int ni = 0; ni < 6; ni++) {
                    int col = wn * 48 + ni * 8 + 2 * t;
                    uint32_t* q = dsm + QA_QK + (col >> 5) * 5120 + nt * 2560 +
                                  ((col & 31) >> 1);
                    if (nt == 0) {
                        q[rAl * 20]       = packbf(acc[mi][ni][0] * qs, acc[mi][ni][1] * qs);
                        q[(rAl + 8) * 20] = packbf(acc[mi][ni][2] * qs, acc[mi][ni][3] * qs);
                    } else {
                        q[rAl * 20]       = packbf(acc[mi][ni][0], acc[mi][ni][1]);
                        q[(rAl + 8) * 20] = packbf(acc[mi][ni][2], acc[mi][ni][3]);
                    }
                }
            }
        } else {
            bf16* vst = (bf16*)(dsm + QA_VST);
#pragma unroll
            for (int mi = 0; mi < 2; mi++) {
                int rAl = wm * 32 + mi * 16 + g;
#pragma unroll
                for (int ni = 0; ni < 6; ni++) {
                    int col = wn * 48 + ni * 8 + 2 * t;
                    bf16* v = vst + (col >> 5) * 4352 + (col & 31) * 136;
                    v[rAl]           = __float2bfloat16(acc[mi][ni][0]);
                    v[136 + rAl]     = __float2bfloat16(acc[mi][ni][1]);
                    v[rAl + 8]       = __float2bfloat16(acc[mi][ni][2]);
                    v[136 + rAl + 8] = __float2bfloat16(acc[mi][ni][3]);
                }
            }
        }
        if (nt < 2) {
            CP_WAIT0();
            __syncthreads();
        }
    }
    __syncthreads();   // QKV smem fully visible

    // ---- attention per head (8 warps x 16 rows) ----
    int R0 = wid * 16;
    uint32_t* o32 = (uint32_t*)attn_out;

#pragma unroll 1
    for (int h = 0; h < 3; h++) {
        uint32_t* Qs  = dsm + QA_QK + h * 5120;
        uint32_t* Ks  = Qs + 2560;
        uint32_t* V32 = dsm + QA_VST + h * 2176;
        uint32_t* Bt  = dsm + ((h == 1) ? QA_BT1 : QA_BT0);

        float accS[16][4];
#pragma unroll
        for (int b = 0; b < 16; b++)
#pragma unroll
            for (int c = 0; c < 4; c++) accS[b][c] = 0.0f;

#pragma unroll
        for (int kk = 0; kk < 2; kk++) {
            uint32_t a0, a1, a2, a3;
            LDSM_X4(a0, a1, a2, a3, a_frag_addr(Qs, 20, R0, kk, lane));
#pragma unroll
            for (int p = 0; p < 8; p++) {
                uint32_t b0, b1, b2, b3;
                LDSM_X4(b0, b1, b2, b3, b_frag_addr(Ks, 20, p * 16, kk, lane));
                MMA_BF16(accS[2 * p],     a0, a1, a2, a3, b0, b1);
                MMA_BF16(accS[2 * p + 1], a0, a1, a2, a3, b2, b3);
            }
        }

        float invA, invB;
        {
            uint32_t baddr = sm_addr(Bt + (R0 + (lane & 15)) * 68);
            float mA = -1e30f, mB = -1e30f;
#pragma unroll
            for (int nj = 0; nj < 16; nj++) {
                uint32_t br0, br1;
                LDSM_X2(br0, br1, baddr + nj * 16);
                float2 fA = unpackbf(br0), fB = unpackbf(br1);
                float v0 = accS[nj][0] + fA.x;
                float v1 = accS[nj][1] + fA.y;
                float v2 = accS[nj][2] + fB.x;
                float v3 = accS[nj][3] + fB.y;
                accS[nj][0] = v0; accS[nj][1] = v1;
                accS[nj][2] = v2; accS[nj][3] = v3;
                mA = fmaxf(mA, fmaxf(v0, v1));
                mB = fmaxf(mB, fmaxf(v2, v3));
            }
            mA = fmaxf(mA, __shfl_xor_sync(0xffffffffu, mA, 1));
            mA = fmaxf(mA, __shfl_xor_sync(0xffffffffu, mA, 2));
            mB = fmaxf(mB, __shfl_xor_sync(0xffffffffu, mB, 1));
            mB = fmaxf(mB, __shfl_xor_sync(0xffffffffu, mB, 2));
            float dA = 0.f, dB = 0.f;
#pragma unroll
            for (int nj = 0; nj < 16; nj++) {
                float p0 = exp2f(accS[nj][0] - mA);
                float p1 = exp2f(accS[nj][1] - mA);
                float p2 = exp2f(accS[nj][2] - mB);
                float p3 = exp2f(accS[nj][3] - mB);
                accS[nj][0] = p0; accS[nj][1] = p1;
                accS[nj][2] = p2; accS[nj][3] = p3;
                dA += p0 + p1; dB += p2 + p3;
            }
            dA += __shfl_xor_sync(0xffffffffu, dA, 1);
            dA += __shfl_xor_sync(0xffffffffu, dA, 2);
            dB += __shfl_xor_sync(0xffffffffu, dB, 1);
            dB += __shfl_xor_sync(0xffffffffu, dB, 2);
            invA = 1.0f / dA;
            invB = 1.0f / dB;
        }

        float accO[4][4];
#pragma unroll
        for (int b = 0; b < 4; b++)
#pragma unroll
            for (int c = 0; c < 4; c++) accO[b][c] = 0.0f;

#pragma unroll
        for (int kkp = 0; kkp < 8; kkp++) {
            uint32_t a0 = packbf(accS[2 * kkp][0],     accS[2 * kkp][1]);
            uint32_t a1 = packbf(accS[2 * kkp][2],     accS[2 * kkp][3]);
            uint32_t a2 = packbf(accS[2 * kkp + 1][0], accS[2 * kkp + 1][1]);
            uint32_t a3 = packbf(accS[2 * kkp + 1][2], accS[2 * kkp + 1][3]);
#pragma unroll
            for (int ni = 0; ni < 4; ni++) {
                int vb = (ni * 8 + g) * 68 + kkp * 8 + t;
                uint32_t b0 = V32[vb], b1 = V32[vb + 4];
                MMA_BF16(accO[ni], a0, a1, a2, a3, b0, b1);
            }
        }

        size_t baseA = ((size_t)bw * 128 + R0 + g) * 48 + h * 16;
        size_t baseB = baseA + 8 * 48;
#pragma unroll
        for (int ni = 0; ni < 4; ni++) {
            int c2 = ni * 4 + t;
            o32[baseA + c2] = packbf(accO[ni][0] * invA, accO[ni][1] * invA);
            o32[baseB + c2] = packbf(accO[ni][2] * invB, accO[ni][3] * invB);
        }

        if (h == 0) {
            __syncthreads();   // all warps done reading Bt0
            const float4* tp = (const float4*)(biasTiles + (size_t)(16 + cls) * 16384);
#pragma unroll
            for (int it = 0; it < 8; it++) {
                int lin = tid + it * 256;
                int r = lin >> 4, c = lin & 15;
                CP_ASYNC16(sm_addr(dsm + QA_BT0 + r * 68 + c * 4), tp + lin);
            }
            CP_COMMIT();
        } else if (h == 1) {
            CP_WAIT0();
            __syncthreads();   // bias head2 landed in Bt0
        }
    }
}

// ============ out-proj + residual scatter + fused LN2 (R13) ======
#define OPJ_DSM (128 * 100 * 4)
__global__ void __launch_bounds__(256)
outproj_ln_kernel(const bf16* __restrict__ A, const uint32_t* __restrict__ BT,
                  float* __restrict__ out, bf16* __restrict__ h2,
                  const float* __restrict__ bias, const float* __restrict__ res,
                  const float* __restrict__ gamma, const float* __restrict__ beta) {
    extern __shared__ uint32_t dsm[];
    uint32_t* As = dsm;
    uint32_t* Bs = dsm + 128 * 52;
    float* rowbuf = (float*)dsm;
    int tid = threadIdx.x;
    int lane = tid & 31, wid = tid >> 5;
    int wm = wid & 3, wn = wid >> 2;
    int g = lane >> 2, t = lane & 3;
    int row0 = blockIdx.x * 128;

    {
        const float4* src = (const float4*)(A + (size_t)row0 * CDIM);
#pragma unroll
        for (int i = 0; i < 6; i++) {
            int lin = tid + i * 256;
            int r = lin / 12, c = lin % 12;
            CP_ASYNC16(sm_addr(As + r * 52 + c * 4), src + lin);
        }
        const float4* bsrc = (const float4*)BT;
#pragma unroll
        for (int i = 0; i < 5; i++) {
            int lin = tid + i * 256;
            if (lin < 1152) {
                int r = lin / 12, c = lin % 12;
                CP_ASYNC16(sm_addr(Bs + r * 52 + c * 4), bsrc + lin);
            }
        }
    }
    CP_COMMIT();
    CP_WAIT0();
    __syncthreads();

    float acc[2][6][4];
#pragma unroll
    for (int a = 0; a < 2; a++)
#pragma unroll
        for (int b = 0; b < 6; b++)
#pragma unroll
            for (int c = 0; c < 4; c++) acc[a][b][c] = 0.0f;

#pragma unroll
    for (int kk = 0; kk < 6; kk++) {
        uint32_t af[2][4];
#pragma unroll
        for (int mi = 0; mi < 2; mi++)
            LDSM_X4(af[mi][0], af[mi][1], af[mi][2], af[mi][3],
                    a_frag_addr(As, 52, wm * 32 + mi * 16, kk, lane));
#pragma unroll
        for (int p = 0; p < 3; p++) {
            uint32_t b0, b1, b2, b3;
            LDSM_X4(b0, b1, b2, b3, b_frag_addr(Bs, 52, wn * 48 + p * 16, kk, lane));
#pragma unroll
            for (int mi = 0; mi < 2; mi++) {
                MMA_BF16(acc[mi][2 * p],     af[mi][0], af[mi][1], af[mi][2], af[mi][3], b0, b1);
                MMA_BF16(acc[mi][2 * p + 1], af[mi][0], af[mi][1], af[mi][2], af[mi][3], b2, b3);
            }
        }
    }
    __syncthreads();

#pragma unroll
    for (int mi = 0; mi < 2; mi++) {
        int lrA = wm * 32 + mi * 16 + g;
        int lrB = lrA + 8;
        size_t natA = nat_index(row0 + lrA) * (size_t)CDIM;
        size_t natB = nat_index(row0 + lrB) * (size_t)CDIM;
#pragma unroll
        for (int ni = 0; ni < 6; ni++) {
            int col = wn * 48 + ni * 8 + 2 * t;
            float b0 = bias[col], b1 = bias[col + 1];
            float2 rx = *(const float2*)(res + natA + col);
            float2 ry = *(const float2*)(res + natB + col);
            *(float2*)(rowbuf + lrA * 100 + col) =
                make_float2(rx.x + acc[mi][ni][0] + b0, rx.y + acc[mi][ni][1] + b1);
            *(float2*)(rowbuf + lrB * 100 + col) =
                make_float2(ry.x + acc[mi][ni][2] + b0, ry.y + acc[mi][ni][3] + b1);
        }
    }
    __syncthreads();

    float ga0 = gamma[lane], ga1 = gamma[lane + 32], ga2 = gamma[lane + 64];
    float be0 = beta[lane],  be1 = beta[lane + 32],  be2 = beta[lane + 64];
#pragma unroll 1
    for (int it = 0; it < 16; it++) {
        int lr = wid * 16 + it;
        size_t nat = nat_index(row0 + lr) * (size_t)CDIM;
        const float* rb = rowbuf + lr * 100;
        float v0 = rb[lane], v1 = rb[lane + 32], v2 = rb[lane + 64];
        float s = v0 + v1 + v2;
#pragma unroll
        for (int o = 16; o; o >>= 1) s += __shfl_xor_sync(0xffffffffu, s, o);
        float mu = s * (1.0f / 96.0f);
        float d0 = v0 - mu, d1 = v1 - mu, d2 = v2 - mu;
        float q = d0 * d0 + d1 * d1 + d2 * d2;
#pragma unroll
        for (int o = 16; o; o >>= 1) q += __shfl_xor_sync(0xffffffffu, q, o);
        float rs = rsqrtf(q * (1.0f / 96.0f) + 1e-5f);
        out[nat + lane]      = v0;
        out[nat + lane + 32] = v1;
        out[nat + lane + 64] = v2;
        h2[nat + lane]      = __float2bfloat16(d0 * rs * ga0 + be0);
        h2[nat + lane + 32] = __float2bfloat16(d1 * rs * ga1 + be1);
        h2[nat + lane + 64] = __float2bfloat16(d2 * rs * ga2 + be2);
    }
}

// ============ fused MLP: cp.async software-pipelined weight chunks (R13) =======
#define MLP_DSM ((128*52 + 128*36 + 64*52 + 96*36) * 4)
__global__ void __launch_bounds__(256)
mlp2_kernel(const bf16* __restrict__ A, float* __restrict__ C,
            const uint32_t* __restrict__ W1T, const float* __restrict__ bias1,
            const uint32_t* __restrict__ W2T, const float* __restrict__ bias2) {
    extern __shared__ uint32_t dsm[];
    uint32_t* As  = dsm;
    uint32_t* Ms  = As + 128 * 52;
    uint32_t* W1b = Ms + 128 * 36;
    uint32_t* W2b = W1b + 64 * 52;
    int tid = threadIdx.x;
    int lane = tid & 31, wid = tid >> 5;
    int wm = wid & 3, wn = wid >> 2;
    int g = lane >> 2, t = lane & 3;
    int row0 = blockIdx.x * 128;

    const float4* w1f4 = (const float4*)W1T;
    const float4* w2f4 = (const float4*)W2T;

    {
        const float4* src = (const float4*)(A + (size_t)row0 * CDIM);
#pragma unroll
        for (int i = 0; i < 6; i++) {
            int lin = tid + i * 256;
            int r = lin / 12, c = lin % 12;
            CP_ASYNC16(sm_addr(As + r * 52 + c * 4), src + lin);
        }
#pragma unroll
        for (int i = 0; i < 3; i++) {
            int lin = tid + i * 256;
            int n = lin / 12, c = lin % 12;
            CP_ASYNC16(sm_addr(W1b + n * 52 + c * 4), w1f4 + (size_t)n * 12 + c);
        }
    }
    CP_COMMIT();
    CP_WAIT0();
    __syncthreads();

    float acc2[2][6][4];
#pragma unroll
    for (int a = 0; a < 2; a++)
#pragma unroll
        for (int b = 0; b < 6; b++)
#pragma unroll
            for (int c = 0; c < 4; c++) acc2[a][b][c] = 0.0f;

#pragma unroll 1
    for (int nt = 0; nt < 6; nt++) {
#pragma unroll
        for (int i = 0; i < 3; i++) {
            int lin = tid + i * 256;
            int n = lin >> 3, c = lin & 7;
            CP_ASYNC16(sm_addr(W2b + n * 36 + c * 4),
                       w2f4 + (size_t)n * 48 + nt * 8 + c);
        }
        CP_COMMIT();

        float acc1[2][4][4];
#pragma unroll
        for (int a = 0; a < 2; a++)
#pragma unroll
            for (int b = 0; b < 4; b++)
#pragma unroll
                for (int c = 0; c < 4; c++) acc1[a][b][c] = 0.0f;

#pragma unroll
        for (int kk = 0; kk < 6; kk++) {
            uint32_t af[2][4];
#pragma unroll
            for (int mi = 0; mi < 2; mi++)
                LDSM_X4(af[mi][0], af[mi][1], af[mi][2], af[mi][3],
                        a_frag_addr(As, 52, wm * 32 + mi * 16, kk, lane));
#pragma unroll
            for (int p = 0; p < 2; p++) {
                uint32_t b0, b1, b2, b3;
                LDSM_X4(b0, b1, b2, b3, b_frag_addr(W1b, 52, wn * 32 + p * 16, kk, lane));
#pragma unroll
                for (int mi = 0; mi < 2; mi++) {
                    MMA_BF16(acc1[mi][2 * p],     af[mi][0], af[mi][1], af[mi][2], af[mi][3], b0, b1);
                    MMA_BF16(acc1[mi][2 * p + 1], af[mi][0], af[mi][1], af[mi][2], af[mi][3], b2, b3);
                }
            }
        }
#pragma unroll
        for (int mi = 0; mi < 2; mi++) {
            int rA = wm * 32 + mi * 16 + g;
#pragma unroll
            for (int ni = 0; ni < 4; ni++) {
                int lc = wn * 32 + ni * 8 + 2 * t;
                float b0 = bias1[nt * 64 + lc], b1 = bias1[nt * 64 + lc + 1];
                int c2 = lc >> 1;
                Ms[rA * 36 + c2] = packbf(gelu_tanh(acc1[mi][ni][0] + b0),
                                          gelu_tanh(acc1[mi][ni][1] + b1));
                Ms[(rA + 8) * 36 + c2] = packbf(gelu_tanh(acc1[mi][ni][2] + b0),
                                                gelu_tanh(acc1[mi][ni][3] + b1));
            }
        }
        CP_WAIT0();
        __syncthreads();

        if (nt < 5) {
#pragma unroll
            for (int i = 0; i < 3; i++) {
                int lin = tid + i * 256;
                int n = lin / 12, c = lin % 12;
                CP_ASYNC16(sm_addr(W1b + n * 52 + c * 4),
                           w1f4 + (size_t)((nt + 1) * 64 + n) * 12 + c);
            }
            CP_COMMIT();
        }

#pragma unroll
        for (int kk = 0; kk < 4; kk++) {
            uint32_t af[2][4];
#pragma unroll
            for (int mi = 0; mi < 2; mi++)
                LDSM_X4(af[mi][0], af[mi][1], af[mi][2], af[mi][3],
                        a_frag_addr(Ms, 36, wm * 32 + mi * 16, kk, lane));
#pragma unroll
            for (int p = 0; p < 3; p++) {
                uint32_t b0, b1, b2, b3;
                LDSM_X4(b0, b1, b2, b3, b_frag_addr(W2b, 36, wn * 48 + p * 16, kk, lane));
#pragma unroll
                for (int mi = 0; mi < 2; mi++) {
                    MMA_BF16(acc2[mi][2 * p],     af[mi][0], af[mi][1], af[mi][2], af[mi][3], b0, b1);
                    MMA_BF16(acc2[mi][2 * p + 1], af[mi][0], af[mi][1], af[mi][2], af[mi][3], b2, b3);
                }
            }
        }
        if (nt < 5) {
            CP_WAIT0();
            __syncthreads();
        }
    }
#pragma unroll
    for (int mi = 0; mi < 2; mi++) {
        int rA = row0 + wm * 32 + mi * 16 + g;
#pragma unroll
        for (int ni = 0; ni < 6; ni++) {
            int cc = wn * 48 + ni * 8 + 2 * t;
            float b0 = bias2[cc], b1 = bias2[cc + 1];
            size_t oA = (size_t)rA * 96 + cc;
            size_t oB = (size_t)(rA + 8) * 96 + cc;
            float2 ca = *(float2*)(C + oA);
            float2 cb = *(float2*)(C + oB);
            *(float2*)(C + oA) = make_float2(ca.x + acc2[mi][ni][0] + b0,
                                             ca.y + acc2[mi][ni][1] + b1);
            *(float2*)(C + oB) = make_float2(cb.x + acc2[mi][ni][2] + b0,
                                             cb.y + acc2[mi][ni][3] + b1);
        }
    }
}

// ---------------- launch ----------------
extern "C" void kernel_launch(void* const* d_in, const int* in_sizes, int n_in,
                              void* d_out, int out_size) {
    const float* x      = (const float*)d_in[0];
    const float* gamma1 = (const float*)d_in[1];
    const float* beta1  = (const float*)d_in[2];
    const float* w_qkv  = (const float*)d_in[3];
    const float* w_out  = (const float*)d_in[4];
    const float* b_out  = (const float*)d_in[5];
    const float* relb   = (const float*)d_in[6];
    const float* gamma2 = (const float*)d_in[7];
    const float* beta2  = (const float*)d_in[8];
    const float* w1     = (const float*)d_in[9];
    const float* b1     = (const float*)d_in[10];
    const float* w2     = (const float*)d_in[11];
    const float* b2     = (const float*)d_in[12];
    float* out = (float*)d_out;

    bf16 *hw, *attn, *h2, *btiles;
    uint32_t *wqkvT, *w1T, *w2T, *woutT;
    cudaGetSymbolAddress((void**)&hw,     g_hw);
    cudaGetSymbolAddress((void**)&attn,   g_attn);
    cudaGetSymbolAddress((void**)&h2,     g_h2);
    cudaGetSymbolAddress((void**)&btiles, g_biasTiles);
    cudaGetSymbolAddress((void**)&wqkvT,  g_wqkvT);
    cudaGetSymbolAddress((void**)&w1T,    g_w1T);
    cudaGetSymbolAddress((void**)&w2T,    g_w2T);
    cudaGetSymbolAddress((void**)&woutT,  g_woutT);

    cudaFuncSetAttribute(qkv_attn_kernel,
                         cudaFuncAttributeMaxDynamicSharedMemorySize, QA_DSM);
    cudaFuncSetAttribute(outproj_ln_kernel,
                         cudaFuncAttributeMaxDynamicSharedMemorySize, OPJ_DSM);
    cudaFuncSetAttribute(mlp2_kernel,
                         cudaFuncAttributeMaxDynamicSharedMemorySize, MLP_DSM);

    convAll<<<(55296 + 255) / 256, 256>>>(w_qkv, w1, w2, w_out,
                                          wqkvT, w1T, w2T, woutT);
    bias_tiles_kernel<<<(24 * 16384) / 256, 256>>>(relb, btiles);

    ln_kernel<true><<<MROWS / 8, 256>>>(x, gamma1, beta1, hw);
    qkv_attn_kernel<<<BATCH * NWIN, 256, QA_DSM>>>(hw, wqkvT, btiles, attn);
    outproj_ln_kernel<<<MROWS / 128, 256, OPJ_DSM>>>(attn, woutT, out, h2,
                                                     b_out, x, gamma2, beta2);
    mlp2_kernel<<<MROWS / 128, 256, MLP_DSM>>>(h2, out, w1T, b1, w2T, b2);
}

// round 17
// speedup vs baseline: 1.2182x; 1.0153x over previous
#include <cuda_runtime.h>
#include <cuda_bf16.h>
#include <math.h>
#include <stdint.h>

// ---------------- static config ----------------
#define BATCH  2
#define CDIM   96
#define HEADS  3
#define INNER  96
#define NWIN   1024
#define NTOK   128
#define MROWS  (BATCH*NWIN*NTOK)   // 262144
#define MLPD   384
#define QKVN   288
#define ATT_SCALE 0.17677669529663687f
#define LOG2E     1.4426950408889634f

typedef __nv_bfloat16 bf16;

// ---------------- scratch ----------------
__device__ bf16 g_hw  [(size_t)MROWS * CDIM];
__device__ bf16 g_attn[(size_t)MROWS * INNER];
__device__ bf16 g_h2  [(size_t)MROWS * CDIM];
__device__ uint32_t g_wqkvT[QKVN * 48];
__device__ uint32_t g_w1T  [MLPD * 48];
__device__ uint32_t g_w2T  [96 * 192];
__device__ uint32_t g_woutT[96 * 48];
__device__ bf16 g_biasTiles[24 * 128 * 128];

__device__ __forceinline__ size_t nat_index(int r) {
    int bb  = r >> 17;
    int rem = r & 131071;
    int wdx = rem >> 7, n = rem & 127;
    int wz = wdx >> 8, wy = (wdx >> 4) & 15, wx = wdx & 15;
    int td = n >> 6,  th = (n >> 3) & 7,   tw = n & 7;
    int sd = (wz * 2 + td + 1) & 7;
    int sh = (wy * 8 + th + 4) & 127;
    int sw = (wx * 8 + tw + 4) & 127;
    return ((((size_t)bb * 8 + sd) << 7) | sh) << 7 | sw;
}

__device__ __forceinline__ float gelu_tanh(float v) {
    float c = v + 0.044715f * v * v * v;
    return 0.5f * v * (1.0f + tanhf(0.7978845608028654f * c));
}

__device__ __forceinline__ uint32_t packbf(float a, float b) {
    __nv_bfloat162 h = __floats2bfloat162_rn(a, b);
    return *reinterpret_cast<uint32_t*>(&h);
}

__device__ __forceinline__ float2 unpackbf(uint32_t u) {
    __nv_bfloat162 h = *reinterpret_cast<__nv_bfloat162*>(&u);
    return __bfloat1622float2(h);
}

__device__ __forceinline__ uint32_t sm_addr(const void* p) {
    return (uint32_t)__cvta_generic_to_shared(p);
}

#define MMA_BF16(d, a0, a1, a2, a3, b0, b1)                                   \
    asm volatile(                                                             \
        "mma.sync.aligned.m16n8k16.row.col.f32.bf16.bf16.f32 "                \
        "{%0,%1,%2,%3}, {%4,%5,%6,%7}, {%8,%9}, {%0,%1,%2,%3};\n"             \
        : "+f"(d[0]), "+f"(d[1]), "+f"(d[2]), "+f"(d[3])                      \
        : "r"(a0), "r"(a1), "r"(a2), "r"(a3), "r"(b0), "r"(b1))

#define LDSM_X4(d0, d1, d2, d3, a)                                            \
    asm volatile("ldmatrix.sync.aligned.m8n8.x4.shared.b16 {%0,%1,%2,%3}, [%4];" \
        : "=r"(d0), "=r"(d1), "=r"(d2), "=r"(d3) : "r"(a))

#define LDSM_X2(d0, d1, a)                                                    \
    asm volatile("ldmatrix.sync.aligned.m8n8.x2.shared.b16 {%0,%1}, [%2];"    \
        : "=r"(d0), "=r"(d1) : "r"(a))

#define CP_ASYNC16(dst, src)                                                  \
    asm volatile("cp.async.cg.shared.global [%0], [%1], 16;"                  \
        :: "r"(dst), "l"(src))
#define CP_COMMIT() asm volatile("cp.async.commit_group;")
#define CP_WAIT0()  asm volatile("cp.async.wait_group 0;")
#define CP_WAIT1()  asm volatile("cp.async.wait_group 1;")

__device__ __forceinline__ uint32_t a_frag_addr(const uint32_t* base, int S,
                                                int R, int kk, int lane) {
    return sm_addr(base + (R + (lane & 15)) * S + kk * 8 + ((lane >> 4) << 2));
}
__device__ __forceinline__ uint32_t b_frag_addr(const uint32_t* base, int S,
                                                int n0, int kk, int lane) {
    return sm_addr(base + (n0 + ((lane >> 4) << 3) + (lane & 7)) * S +
                   kk * 8 + (((lane >> 3) & 1) << 2));
}

// ---------------- merged weight convert ----------------
__global__ void convAll(const float* __restrict__ wqkv, const float* __restrict__ w1,
                        const float* __restrict__ w2, const float* __restrict__ wout,
                        uint32_t* __restrict__ oqkv, uint32_t* __restrict__ o1,
                        uint32_t* __restrict__ o2, uint32_t* __restrict__ oo) {
    int idx = blockIdx.x * 256 + threadIdx.x;
    if (idx < 13824) {
        int n = idx / 48, c = idx - n * 48;
        oqkv[idx] = packbf(wqkv[(2 * c) * QKVN + n], wqkv[(2 * c + 1) * QKVN + n]);
    } else if ((idx -= 13824) < 18432) {
        int n = idx / 48, c = idx - n * 48;
        o1[idx] = packbf(w1[(2 * c) * MLPD + n], w1[(2 * c + 1) * MLPD + n]);
    } else if ((idx -= 18432) < 18432) {
        int n = idx / 192, c = idx - n * 192;
        o2[idx] = packbf(w2[(2 * c) * 96 + n], w2[(2 * c + 1) * 96 + n]);
    } else if ((idx -= 18432) < 4608) {
        int n = idx / 48, c = idx - n * 48;
        oo[idx] = packbf(wout[(2 * c) * 96 + n], wout[(2 * c + 1) * 96 + n]);
    }
}

// ---------------- bias+mask tile precompute ----------------
__global__ void bias_tiles_kernel(const float* __restrict__ relb,
                                  bf16* __restrict__ tiles) {
    int idx = blockIdx.x * 256 + threadIdx.x;
    int tile = idx >> 14;
    int rem  = idx & 16383;
    int ii = rem >> 7, jj = rem & 127;
    int head = tile >> 3, cls = tile & 7;
    int di = ii >> 6, hi = (ii >> 3) & 7, wi = ii & 7;
    int dj = jj >> 6, hj = (jj >> 3) & 7, wj = jj & 7;
    int ri = ((cls & 4) ? (1 + di) : 0) * 9 +
             ((cls & 2) ? ((hi < 4) ? 1 : 2) : 0) * 3 +
             ((cls & 1) ? ((wi < 4) ? 1 : 2) : 0);
    int rj = ((cls & 4) ? (1 + dj) : 0) * 9 +
             ((cls & 2) ? ((hj < 4) ? 1 : 2) : 0) * 3 +
             ((cls & 1) ? ((wj < 4) ? 1 : 2) : 0);
    int bidx = (di - dj + 1) * 225 + (hi - hj + 7) * 15 + (wi - wj + 7);
    float v = relb[bidx * 3 + head] * LOG2E + (ri == rj ? 0.f : -1e9f);
    tiles[idx] = __float2bfloat16(v);
}

// ---------------- LayerNorm (warp per token), bf16 output ----------------
template<bool GATHER>
__global__ void ln_kernel(const float* __restrict__ x,
                          const float* __restrict__ gamma,
                          const float* __restrict__ beta,
                          bf16* __restrict__ out) {
    int warp = (blockIdx.x * blockDim.x + threadIdx.x) >> 5;
    int lane = threadIdx.x & 31;
    if (warp >= MROWS) return;
    size_t src = GATHER ? nat_index(warp) : (size_t)warp;
    const float* xp = x + src * CDIM;
    float v0 = xp[lane], v1 = xp[lane + 32], v2 = xp[lane + 64];
    float s = v0 + v1 + v2;
#pragma unroll
    for (int o = 16; o; o >>= 1) s += __shfl_xor_sync(0xffffffffu, s, o);
    float mu = s * (1.0f / 96.0f);
    float d0 = v0 - mu, d1 = v1 - mu, d2 = v2 - mu;
    float q = d0 * d0 + d1 * d1 + d2 * d2;
#pragma unroll
    for (int o = 16; o; o >>= 1) q += __shfl_xor_sync(0xffffffffu, q, o);
    float rs = rsqrtf(q * (1.0f / 96.0f) + 1e-5f);
    bf16* op = out + (size_t)warp * CDIM;
    op[lane]      = __float2bfloat16(d0 * rs * gamma[lane]      + beta[lane]);
    op[lane + 32] = __float2bfloat16(d1 * rs * gamma[lane + 32] + beta[lane + 32]);
    op[lane + 64] = __float2bfloat16(d2 * rs * gamma[lane + 64] + beta[lane + 64]);
}

// ============ FUSED qkv GEMM + 3-head attention, 384 threads, heads parallel ===
// smem u32 layout (Q/K stride 20 u32 = 80B, 16B-aligned for ldmatrix):
//  QK   [0, 15360):      3 heads x (Q 128x20 | K 128x20), head stride 5120
//  VST  [15360, 21888):  3 heads x V^T 32x136 bf16 (2176 u32)
//  BT0  [21888, 30592):  bias head0 (prefetched at start)
//  UN   [30592, 48000):  union { As(6656)+Bs0(4992)+Bs1(4992)=16640 | BT1(8704)+BT2(8704)=17408 }
#define QA_QK   0
#define QA_VST  15360
#define QA_BT0  21888
#define QA_UN   30592
#define QA_DSM  (48000 * 4)   // 192000 B

__global__ void __launch_bounds__(384)
qkv_attn_kernel(const bf16* __restrict__ A, const uint32_t* __restrict__ BT,
                const bf16* __restrict__ biasTiles,
                bf16* __restrict__ attn_out) {
    extern __shared__ uint32_t dsm[];
    int bw  = blockIdx.x;
    int w   = bw & (NWIN - 1);
    int tid = threadIdx.x;
    int lane = tid & 31, wid = tid >> 5;
    int g = lane >> 2, t = lane & 3;
    int row0 = bw * 128;

    int cls = (((w >> 8) == 3) ? 4 : 0) | ((((w >> 4) & 15) == 15) ? 2 : 0) |
              (((w & 15) == 15) ? 1 : 0);

    uint32_t* As = dsm + QA_UN;
    uint32_t* Bsb[2] = { dsm + QA_UN + 6656, dsm + QA_UN + 11648 };

    // G1: A tile + B tile 0
    {
        const float4* src = (const float4*)(A + (size_t)row0 * CDIM);
#pragma unroll
        for (int i = 0; i < 4; i++) {          // 1536 f4
            int lin = tid + i * 384;
            int r = lin / 12, c = lin % 12;
            CP_ASYNC16(sm_addr(As + r * 52 + c * 4), src + lin);
        }
        const float4* bsrc = (const float4*)BT;
#pragma unroll
        for (int i = 0; i < 3; i++) {          // 1152 f4
            int lin = tid + i * 384;
            int r = lin / 12, c = lin % 12;
            CP_ASYNC16(sm_addr(Bsb[0] + r * 52 + c * 4), bsrc + lin);
        }
    }
    CP_COMMIT();
    // G2: bias head0 (lands under the GEMM)
    {
        const float4* tp = (const float4*)(biasTiles + (size_t)(0 * 8 + cls) * 16384);
#pragma unroll
        for (int it = 0; it < 6; it++) {       // 2048 f4
            int lin = tid + it * 384;
            if (lin < 2048) {
                int r = lin >> 4, c = lin & 15;
                CP_ASYNC16(sm_addr(dsm + QA_BT0 + r * 68 + c * 4), tp + lin);
            }
        }
        CP_COMMIT();
    }
    CP_WAIT1();            // G1 done; bias0 may still fly
    __syncthreads();

    const float qs = ATT_SCALE * LOG2E;
    int wm = wid & 3, wn = wid >> 2;          // 4m x 3n

    // ---- qkv GEMM: 3 column tiles (Q | K | V) ----
#pragma unroll 1
    for (int nt = 0; nt < 3; nt++) {
        uint32_t* Bs = Bsb[nt & 1];
        if (nt < 2) {
            const float4* src = (const float4*)(BT + (size_t)(nt + 1) * 96 * 48);
            uint32_t* Bn = Bsb[(nt + 1) & 1];
#pragma unroll
            for (int i = 0; i < 3; i++) {
                int lin = tid + i * 384;
                int r = lin / 12, c = lin % 12;
                CP_ASYNC16(sm_addr(Bn + r * 52 + c * 4), src + lin);
            }
            CP_COMMIT();
        }

        float acc[2][4][4];
#pragma unroll
        for (int a = 0; a < 2; a++)
#pragma unroll
            for (int b = 0; b < 4; b++)
#pragma unroll
                for (int c = 0; c < 4; c++) acc[a][b][c] = 0.0f;

#pragma unroll
        for (int kk = 0; kk < 6; kk++) {
            uint32_t af[2][4];
#pragma unroll
            for (int mi = 0; mi < 2; mi++)
                LDSM_X4(af[mi][0], af[mi][1], af[mi][2], af[mi][3],
                        a_frag_addr(As, 52, wm * 32 + mi * 16, kk, lane));
#pragma unroll
            for (int p = 0; p < 2; p++) {
                uint32_t b0, b1, b2, b3;
                LDSM_X4(b0, b1, b2, b3,
                        b_frag_addr(Bs, 52, wn * 32 + p * 16, kk, lane));
#pragma unroll
                for (int mi = 0; mi < 2; mi++) {
                    MMA_BF16(acc[mi][2 * p],     af[mi][0], af[mi][1], af[mi][2], af[mi][3], b0, b1);
                    MMA_BF16(acc[mi][2 * p + 1], af[mi][0], af[mi][1], af[mi][2], af[mi][3], b2, b3);
                }
            }
        }

        if (nt == 2) {
            // all warps done with As/Bs -> safe to overwrite union with bias1/2
            __syncthreads();
#pragma unroll
            for (int h = 1; h < 3; h++) {
                const float4* tp = (const float4*)(biasTiles + (size_t)(h * 8 + cls) * 16384);
                uint32_t* Bt = dsm + QA_UN + (h - 1) * 8704;
#pragma unroll
                for (int it = 0; it < 6; it++) {
                    int lin = tid + it * 384;
                    if (lin < 2048) {
                        int r = lin >> 4, c = lin & 15;
                        CP_ASYNC16(sm_addr(Bt + r * 68 + c * 4), tp + lin);
                    }
                }
            }
            CP_COMMIT();
        }

        // epilogue -> smem (Q scaled, K plain, V transposed)
        if (nt < 2) {
#pragma unroll
            for (int mi = 0; mi < 2; mi++) {
                int rAl = wm * 32 + mi * 16 + g;
#pragma unroll
                for (int ni = 0; ni < 4; ni++) {
                    int col = wn * 32 + ni * 8 + 2 * t;
                    int head = col >> 5, c = col & 31;
                    uint32_t* q = dsm + QA_QK + head * 5120 + nt * 2560 + (c >> 1);
                    if (nt == 0) {
                        q[rAl * 20]       = packbf(acc[mi][ni][0] * qs, acc[mi][ni][1] * qs);
                        q[(rAl + 8) * 20] = packbf(acc[mi][ni][2] * qs, acc[mi][ni][3] * qs);
                    } else {
                        q[rAl * 20]       = packbf(acc[mi][ni][0], acc[mi][ni][1]);
                        q[(rAl + 8) * 20] = packbf(acc[mi][ni][2], acc[mi][ni][3]);
                    }
                }
            }
            CP_WAIT0();      // next B landed (bias0 committed earlier also done)
            __syncthreads();
        } else {
            bf16* vst = (bf16*)(dsm + QA_VST);
#pragma unroll
            for (int mi = 0; mi < 2; mi++) {
                int rAl = wm * 32 + mi * 16 + g;
#pragma unroll
                for (int ni = 0; ni < 4; ni++) {
                    int col = wn * 32 + ni * 8 + 2 * t;
                    int head = col >> 5, c = col & 31;
                    bf16* v = vst + head * 4352 + c * 136;
                    v[rAl]           = __float2bfloat16(acc[mi][ni][0]);
                    v[136 + rAl]     = __float2bfloat16(acc[mi][ni][1]);
                    v[rAl + 8]       = __float2bfloat16(acc[mi][ni][2]);
                    v[136 + rAl + 8] = __float2bfloat16(acc[mi][ni][3]);
                }
            }
            CP_WAIT0();      // bias1/2 landed
            __syncthreads(); // QKV + all biases visible
        }
    }

    // ---- attention: 4 warps per head, heads concurrent, no syncs ----
    int head = wid >> 2;          // 0..2
    int wq   = wid & 3;
    uint32_t* Qs  = dsm + QA_QK + head * 5120;
    uint32_t* Ks  = Qs + 2560;
    uint32_t* V32 = dsm + QA_VST + head * 2176;
    uint32_t* Bt  = (head == 0) ? (dsm + QA_BT0) : (dsm + QA_UN + (head - 1) * 8704);
    uint32_t* o32 = (uint32_t*)attn_out;

#pragma unroll 1
    for (int ch = 0; ch < 2; ch++) {
        int R0 = wq * 32 + ch * 16;

        float accS[16][4];
#pragma unroll
        for (int b = 0; b < 16; b++)
#pragma unroll
            for (int c = 0; c < 4; c++) accS[b][c] = 0.0f;

#pragma unroll
        for (int kk = 0; kk < 2; kk++) {
            uint32_t a0, a1, a2, a3;
            LDSM_X4(a0, a1, a2, a3, a_frag_addr(Qs, 20, R0, kk, lane));
#pragma unroll
            for (int p = 0; p < 8; p++) {
                uint32_t b0, b1, b2, b3;
                LDSM_X4(b0, b1, b2, b3, b_frag_addr(Ks, 20, p * 16, kk, lane));
                MMA_BF16(accS[2 * p],     a0, a1, a2, a3, b0, b1);
                MMA_BF16(accS[2 * p + 1], a0, a1, a2, a3, b2, b3);
            }
        }

        float invA, invB;
        {
            uint32_t baddr = sm_addr(Bt + (R0 + (lane & 15)) * 68);
            float mA = -1e30f, mB = -1e30f;
#pragma unroll
            for (int nj = 0; nj < 16; nj++) {
                uint32_t br0, br1;
                LDSM_X2(br0, br1, baddr + nj * 16);
                float2 fA = unpackbf(br0), fB = unpackbf(br1);
                float v0 = accS[nj][0] + fA.x;
                float v1 = accS[nj][1] + fA.y;
                float v2 = accS[nj][2] + fB.x;
                float v3 = accS[nj][3] + fB.y;
                accS[nj][0] = v0; accS[nj][1] = v1;
                accS[nj][2] = v2; accS[nj][3] = v3;
                mA = fmaxf(mA, fmaxf(v0, v1));
                mB = fmaxf(mB, fmaxf(v2, v3));
            }
            mA = fmaxf(mA, __shfl_xor_sync(0xffffffffu, mA, 1));
            mA = fmaxf(mA, __shfl_xor_sync(0xffffffffu, mA, 2));
            mB = fmaxf(mB, __shfl_xor_sync(0xffffffffu, mB, 1));
            mB = fmaxf(mB, __shfl_xor_sync(0xffffffffu, mB, 2));
            float dA = 0.f, dB = 0.f;
#pragma unroll
            for (int nj = 0; nj < 16; nj++) {
                float p0 = exp2f(accS[nj][0] - mA);
                float p1 = exp2f(accS[nj][1] - mA);
                float p2 = exp2f(accS[nj][2] - mB);
                float p3 = exp2f(accS[nj][3] - mB);
                accS[nj][0] = p0; accS[nj][1] = p1;
                accS[nj][2] = p2; accS[nj][3] = p3;
                dA += p0 + p1; dB += p2 + p3;
            }
            dA += __shfl_xor_sync(0xffffffffu, dA, 1);
            dA += __shfl_xor_sync(0xffffffffu, dA, 2);
            dB += __shfl_xor_sync(0xffffffffu, dB, 1);
            dB += __shfl_xor_sync(0xffffffffu, dB, 2);
            invA = 1.0f / dA;
            invB = 1.0f / dB;
        }

        float accO[4][4];
#pragma unroll
        for (int b = 0; b < 4; b++)
#pragma unroll
            for (int c = 0; c < 4; c++) accO[b][c] = 0.0f;

#pragma unroll
        for (int kkp = 0; kkp < 8; kkp++) {
            uint32_t a0 = packbf(accS[2 * kkp][0],     accS[2 * kkp][1]);
            uint32_t a1 = packbf(accS[2 * kkp][2],     accS[2 * kkp][3]);
            uint32_t a2 = packbf(accS[2 * kkp + 1][0], accS[2 * kkp + 1][1]);
            uint32_t a3 = packbf(accS[2 * kkp + 1][2], accS[2 * kkp + 1][3]);
#pragma unroll
            for (int ni = 0; ni < 4; ni++) {
                int vb = (ni * 8 + g) * 68 + kkp * 8 + t;
                uint32_t b0 = V32[vb], b1 = V32[vb + 4];
                MMA_BF16(accO[ni], a0, a1, a2, a3, b0, b1);
            }
        }

        size_t baseA = ((size_t)bw * 128 + R0 + g) * 48 + head * 16;
        size_t baseB = baseA + 8 * 48;
#pragma unroll
        for (int ni = 0; ni < 4; ni++) {
            int c2 = ni * 4 + t;
            o32[baseA + c2] = packbf(accO[ni][0] * invA, accO[ni][1] * invA);
            o32[baseB + c2] = packbf(accO[ni][2] * invB, accO[ni][3] * invB);
        }
    }
}

// ============ out-proj + residual scatter + fused LN2 ======
#define OPJ_DSM (128 * 100 * 4)
__global__ void __launch_bounds__(256)
outproj_ln_kernel(const bf16* __restrict__ A, const uint32_t* __restrict__ BT,
                  float* __restrict__ out, bf16* __restrict__ h2,
                  const float* __restrict__ bias, const float* __restrict__ res,
                  const float* __restrict__ gamma, const float* __restrict__ beta) {
    extern __shared__ uint32_t dsm[];
    uint32_t* As = dsm;
    uint32_t* Bs = dsm + 128 * 52;
    float* rowbuf = (float*)dsm;
    int tid = threadIdx.x;
    int lane = tid & 31, wid = tid >> 5;
    int wm = wid & 3, wn = wid >> 2;
    int g = lane >> 2, t = lane & 3;
    int row0 = blockIdx.x * 128;

    {
        const float4* src = (const float4*)(A + (size_t)row0 * CDIM);
#pragma unroll
        for (int i = 0; i < 6; i++) {
            int lin = tid + i * 256;
            int r = lin / 12, c = lin % 12;
            CP_ASYNC16(sm_addr(As + r * 52 + c * 4), src + lin);
        }
        const float4* bsrc = (const float4*)BT;
#pragma unroll
        for (int i = 0; i < 5; i++) {
            int lin = tid + i * 256;
            if (lin < 1152) {
                int r = lin / 12, c = lin % 12;
                CP_ASYNC16(sm_addr(Bs + r * 52 + c * 4), bsrc + lin);
            }
        }
    }
    CP_COMMIT();
    CP_WAIT0();
    __syncthreads();

    float acc[2][6][4];
#pragma unroll
    for (int a = 0; a < 2; a++)
#pragma unroll
        for (int b = 0; b < 6; b++)
#pragma unroll
            for (int c = 0; c < 4; c++) acc[a][b][c] = 0.0f;

#pragma unroll
    for (int kk = 0; kk < 6; kk++) {
        uint32_t af[2][4];
#pragma unroll
        for (int mi = 0; mi < 2; mi++)
            LDSM_X4(af[mi][0], af[mi][1], af[mi][2], af[mi][3],
                    a_frag_addr(As, 52, wm * 32 + mi * 16, kk, lane));
#pragma unroll
        for (int p = 0; p < 3; p++) {
            uint32_t b0, b1, b2, b3;
            LDSM_X4(b0, b1, b2, b3, b_frag_addr(Bs, 52, wn * 48 + p * 16, kk, lane));
#pragma unroll
            for (int mi = 0; mi < 2; mi++) {
                MMA_BF16(acc[mi][2 * p],     af[mi][0], af[mi][1], af[mi][2], af[mi][3], b0, b1);
                MMA_BF16(acc[mi][2 * p + 1], af[mi][0], af[mi][1], af[mi][2], af[mi][3], b2, b3);
            }
        }
    }
    __syncthreads();

#pragma unroll
    for (int mi = 0; mi < 2; mi++) {
        int lrA = wm * 32 + mi * 16 + g;
        int lrB = lrA + 8;
        size_t natA = nat_index(row0 + lrA) * (size_t)CDIM;
        size_t natB = nat_index(row0 + lrB) * (size_t)CDIM;
#pragma unroll
        for (int ni = 0; ni < 6; ni++) {
            int col = wn * 48 + ni * 8 + 2 * t;
            float b0 = bias[col], b1 = bias[col + 1];
            float2 rx = *(const float2*)(res + natA + col);
            float2 ry = *(const float2*)(res + natB + col);
            *(float2*)(rowbuf + lrA * 100 + col) =
                make_float2(rx.x + acc[mi][ni][0] + b0, rx.y + acc[mi][ni][1] + b1);
            *(float2*)(rowbuf + lrB * 100 + col) =
                make_float2(ry.x + acc[mi][ni][2] + b0, ry.y + acc[mi][ni][3] + b1);
        }
    }
    __syncthreads();

    float ga0 = gamma[lane], ga1 = gamma[lane + 32], ga2 = gamma[lane + 64];
    float be0 = beta[lane],  be1 = beta[lane + 32],  be2 = beta[lane + 64];
#pragma unroll 1
    for (int it = 0; it < 16; it++) {
        int lr = wid * 16 + it;
        size_t nat = nat_index(row0 + lr) * (size_t)CDIM;
        const float* rb = rowbuf + lr * 100;
        float v0 = rb[lane], v1 = rb[lane + 32], v2 = rb[lane + 64];
        float s = v0 + v1 + v2;
#pragma unroll
        for (int o = 16; o; o >>= 1) s += __shfl_xor_sync(0xffffffffu, s, o);
        float mu = s * (1.0f / 96.0f);
        float d0 = v0 - mu, d1 = v1 - mu, d2 = v2 - mu;
        float q = d0 * d0 + d1 * d1 + d2 * d2;
#pragma unroll
        for (int o = 16; o; o >>= 1) q += __shfl_xor_sync(0xffffffffu, q, o);
        float rs = rsqrtf(q * (1.0f / 96.0f) + 1e-5f);
        out[nat + lane]      = v0;
        out[nat + lane + 32] = v1;
        out[nat + lane + 64] = v2;
        h2[nat + lane]      = __float2bfloat16(d0 * rs * ga0 + be0);
        h2[nat + lane + 32] = __float2bfloat16(d1 * rs * ga1 + be1);
        h2[nat + lane + 64] = __float2bfloat16(d2 * rs * ga2 + be2);
    }
}

// ============ fused MLP: cp.async software-pipelined weight chunks =======
#define MLP_DSM ((128*52 + 128*36 + 64*52 + 96*36) * 4)
__global__ void __launch_bounds__(256)
mlp2_kernel(const bf16* __restrict__ A, float* __restrict__ C,
            const uint32_t* __restrict__ W1T, const float* __restrict__ bias1,
            const uint32_t* __restrict__ W2T, const float* __restrict__ bias2) {
    extern __shared__ uint32_t dsm[];
    uint32_t* As  = dsm;
    uint32_t* Ms  = As + 128 * 52;
    uint32_t* W1b = Ms + 128 * 36;
    uint32_t* W2b = W1b + 64 * 52;
    int tid = threadIdx.x;
    int lane = tid & 31, wid = tid >> 5;
    int wm = wid & 3, wn = wid >> 2;
    int g = lane >> 2, t = lane & 3;
    int row0 = blockIdx.x * 128;

    const float4* w1f4 = (const float4*)W1T;
    const float4* w2f4 = (const float4*)W2T;

    {
        const float4* src = (const float4*)(A + (size_t)row0 * CDIM);
#pragma unroll
        for (int i = 0; i < 6; i++) {
            int lin = tid + i * 256;
            int r = lin / 12, c = lin % 12;
            CP_ASYNC16(sm_addr(As + r * 52 + c * 4), src + lin);
        }
#pragma unroll
        for (int i = 0; i < 3; i++) {
            int lin = tid + i * 256;
            int n = lin / 12, c = lin % 12;
            CP_ASYNC16(sm_addr(W1b + n * 52 + c * 4), w1f4 + (size_t)n * 12 + c);
        }
    }
    CP_COMMIT();
    CP_WAIT0();
    __syncthreads();

    float acc2[2][6][4];
#pragma unroll
    for (int a = 0; a < 2; a++)
#pragma unroll
        for (int b = 0; b < 6; b++)
#pragma unroll
            for (int c = 0; c < 4; c++) acc2[a][b][c] = 0.0f;

#pragma unroll 1
    for (int nt = 0; nt < 6; nt++) {
#pragma unroll
        for (int i = 0; i < 3; i++) {
            int lin = tid + i * 256;
            int n = lin >> 3, c = lin & 7;
            CP_ASYNC16(sm_addr(W2b + n * 36 + c * 4),
                       w2f4 + (size_t)n * 48 + nt * 8 + c);
        }
        CP_COMMIT();

        float acc1[2][4][4];
#pragma unroll
        for (int a = 0; a < 2; a++)
#pragma unroll
            for (int b = 0; b < 4; b++)
#pragma unroll
                for (int c = 0; c < 4; c++) acc1[a][b][c] = 0.0f;

#pragma unroll
        for (int kk = 0; kk < 6; kk++) {
            uint32_t af[2][4];
#pragma unroll
            for (int mi = 0; mi < 2; mi++)
                LDSM_X4(af[mi][0], af[mi][1], af[mi][2], af[mi][3],
                        a_frag_addr(As, 52, wm * 32 + mi * 16, kk, lane));
#pragma unroll
            for (int p = 0; p < 2; p++) {
                uint32_t b0, b1, b2, b3;
                LDSM_X4(b0, b1, b2, b3, b_frag_addr(W1b, 52, wn * 32 + p * 16, kk, lane));
#pragma unroll
                for (int mi = 0; mi < 2; mi++) {
                    MMA_BF16(acc1[mi][2 * p],     af[mi][0], af[mi][1], af[mi][2], af[mi][3], b0, b1);
                    MMA_BF16(acc1[mi][2 * p + 1], af[mi][0], af[mi][1], af[mi][2], af[mi][3], b2, b3);
                }
            }
        }
#pragma unroll
        for (int mi = 0; mi < 2; mi++) {
            int rA = wm * 32 + mi * 16 + g;
#pragma unroll
            for (int ni = 0; ni < 4; ni++) {
                int lc = wn * 32 + ni * 8 + 2 * t;
                float b0 = bias1[nt * 64 + lc], b1 = bias1[nt * 64 + lc + 1];
                int c2 = lc >> 1;
                Ms[rA * 36 + c2] = packbf(gelu_tanh(acc1[mi][ni][0] + b0),
                                          gelu_tanh(acc1[mi][ni][1] + b1));
                Ms[(rA + 8) * 36 + c2] = packbf(gelu_tanh(acc1[mi][ni][2] + b0),
                                                gelu_tanh(acc1[mi][ni][3] + b1));
            }
        }
        CP_WAIT0();
        __syncthreads();

        if (nt < 5) {
#pragma unroll
            for (int i = 0; i < 3; i++) {
                int lin = tid + i * 256;
                int n = lin / 12, c = lin % 12;
                CP_ASYNC16(sm_addr(W1b + n * 52 + c * 4),
                           w1f4 + (size_t)((nt + 1) * 64 + n) * 12 + c);
            }
            CP_COMMIT();
        }

#pragma unroll
        for (int kk = 0; kk < 4; kk++) {
            uint32_t af[2][4];
#pragma unroll
            for (int mi = 0; mi < 2; mi++)
                LDSM_X4(af[mi][0], af[mi][1], af[mi][2], af[mi][3],
                        a_frag_addr(Ms, 36, wm * 32 + mi * 16, kk, lane));
#pragma unroll
            for (int p = 0; p < 3; p++) {
                uint32_t b0, b1, b2, b3;
                LDSM_X4(b0, b1, b2, b3, b_frag_addr(W2b, 36, wn * 48 + p * 16, kk, lane));
#pragma unroll
                for (int mi = 0; mi < 2; mi++) {
                    MMA_BF16(acc2[mi][2 * p],     af[mi][0], af[mi][1], af[mi][2], af[mi][3], b0, b1);
                    MMA_BF16(acc2[mi][2 * p + 1], af[mi][0], af[mi][1], af[mi][2], af[mi][3], b2, b3);
                }
            }
        }
        if (nt < 5) {
            CP_WAIT0();
            __syncthreads();
        }
    }
#pragma unroll
    for (int mi = 0; mi < 2; mi++) {
        int rA = row0 + wm * 32 + mi * 16 + g;
#pragma unroll
        for (int ni = 0; ni < 6; ni++) {
            int cc = wn * 48 + ni * 8 + 2 * t;
            float b0 = bias2[cc], b1 = bias2[cc + 1];
            size_t oA = (size_t)rA * 96 + cc;
            size_t oB = (size_t)(rA + 8) * 96 + cc;
            float2 ca = *(float2*)(C + oA);
            float2 cb = *(float2*)(C + oB);
            *(float2*)(C + oA) = make_float2(ca.x + acc2[mi][ni][0] + b0,
                                             ca.y + acc2[mi][ni][1] + b1);
            *(float2*)(C + oB) = make_float2(cb.x + acc2[mi][ni][2] + b0,
                                             cb.y + acc2[mi][ni][3] + b1);
        }
    }
}

// ---------------- launch ----------------
extern "C" void kernel_launch(void* const* d_in, const int* in_sizes, int n_in,
                              void* d_out, int out_size) {
    const float* x      = (const float*)d_in[0];
    const float* gamma1 = (const float*)d_in[1];
    const float* beta1  = (const float*)d_in[2];
    const float* w_qkv  = (const float*)d_in[3];
    const float* w_out  = (const float*)d_in[4];
    const float* b_out  = (const float*)d_in[5];
    const float* relb   = (const float*)d_in[6];
    const float* gamma2 = (const float*)d_in[7];
    const float* beta2  = (const float*)d_in[8];
    const float* w1     = (const float*)d_in[9];
    const float* b1     = (const float*)d_in[10];
    const float* w2     = (const float*)d_in[11];
    const float* b2     = (const float*)d_in[12];
    float* out = (float*)d_out;

    bf16 *hw, *attn, *h2, *btiles;
    uint32_t *wqkvT, *w1T, *w2T, *woutT;
    cudaGetSymbolAddress((void**)&hw,     g_hw);
    cudaGetSymbolAddress((void**)&attn,   g_attn);
    cudaGetSymbolAddress((void**)&h2,     g_h2);
    cudaGetSymbolAddress((void**)&btiles, g_biasTiles);
    cudaGetSymbolAddress((void**)&wqkvT,  g_wqkvT);
    cudaGetSymbolAddress((void**)&w1T,    g_w1T);
    cudaGetSymbolAddress((void**)&w2T,    g_w2T);
    cudaGetSymbolAddress((void**)&woutT,  g_woutT);

    cudaFuncSetAttribute(qkv_attn_kernel,
                         cudaFuncAttributeMaxDynamicSharedMemorySize, QA_DSM);
    cudaFuncSetAttribute(outproj_ln_kernel,
                         cudaFuncAttributeMaxDynamicSharedMemorySize, OPJ_DSM);
    cudaFuncSetAttribute(mlp2_kernel,
                         cudaFuncAttributeMaxDynamicSharedMemorySize, MLP_DSM);

    convAll<<<(55296 + 255) / 256, 256>>>(w_qkv, w1, w2, w_out,
                                          wqkvT, w1T, w2T, woutT);
    bias_tiles_kernel<<<(24 * 16384) / 256, 256>>>(relb, btiles);

    ln_kernel<true><<<MROWS / 8, 256>>>(x, gamma1, beta1, hw);
    qkv_attn_kernel<<<BATCH * NWIN, 384, QA_DSM>>>(hw, wqkvT, btiles, attn);
    outproj_ln_kernel<<<MROWS / 128, 256, OPJ_DSM>>>(attn, woutT, out, h2,
                                                     b_out, x, gamma2, beta2);
    mlp2_kernel<<<MROWS / 128, 256, MLP_DSM>>>(h2, out, w1T, b1, w2T, b2);
}